// round 4
// baseline (speedup 1.0000x reference)
#include <cuda_runtime.h>
#include <math.h>

// Problem constants (match reference)
#define B_TOK 8192
#define DIN   1024
#define HID   2048
#define DOUT  1024
#define NEXP  8
#define GHID  1024
#define CAP   8192   // worst-case tokens per expert

// -------- device scratch (static globals; allocation-free) --------
__device__ float g_g1[(size_t)B_TOK * GHID];          //  32 MB  gating hidden
__device__ float g_H  [(size_t)NEXP * CAP * HID];     // 512 MB  relu(x@w1+b1) per pair slot
__device__ float g_MID[(size_t)NEXP * CAP * HID];     // 512 MB  relu(h@w2 + x@wp + b2+bp)
__device__ float g_PO [(size_t)NEXP * CAP * DOUT];    // 256 MB  expert outputs per pair slot
__device__ int   g_count[NEXP];
__device__ int   g_tok[NEXP * CAP];                   // token id per pair slot
__device__ int   g_pairpos[B_TOK * 2];                // token -> its 2 pair slots
__device__ float g_pairw [B_TOK * 2];                 // token -> its 2 softmax weights

// =================================================================
// Reset per-expert counters (must run every graph replay)
// =================================================================
__global__ void reset_counts_kernel() {
    if (threadIdx.x < NEXP) g_count[threadIdx.x] = 0;
}

// =================================================================
// Gating epilogue: logits = relu_g1 @ gw2 + gb2 ; top-2 ; softmax ;
// scatter (token, weight) into per-expert segments.
// One block (128 thr) per token.
// =================================================================
__global__ void gating_topk_scatter_kernel(const float* __restrict__ gw2,
                                           const float* __restrict__ gb2) {
    const int t   = blockIdx.x;
    const int tid = threadIdx.x;

    float acc[NEXP];
#pragma unroll
    for (int e = 0; e < NEXP; e++) acc[e] = 0.f;

    const float* row = g_g1 + (size_t)t * GHID;
    for (int k = tid; k < GHID; k += 128) {
        float v = row[k];
        const float* w = gw2 + (size_t)k * NEXP;
#pragma unroll
        for (int e = 0; e < NEXP; e++) acc[e] += v * w[e];
    }

    __shared__ float sm[128 * NEXP];
#pragma unroll
    for (int e = 0; e < NEXP; e++) sm[tid * NEXP + e] = acc[e];
    __syncthreads();
    for (int s = 64; s > 0; s >>= 1) {
        if (tid < s) {
#pragma unroll
            for (int e = 0; e < NEXP; e++)
                sm[tid * NEXP + e] += sm[(tid + s) * NEXP + e];
        }
        __syncthreads();
    }

    if (tid == 0) {
        float l[NEXP];
#pragma unroll
        for (int e = 0; e < NEXP; e++) l[e] = sm[e] + gb2[e];

        int i0 = 0;
#pragma unroll
        for (int e = 1; e < NEXP; e++) if (l[e] > l[i0]) i0 = e;
        int i1 = -1;
#pragma unroll
        for (int e = 0; e < NEXP; e++) {
            if (e == i0) continue;
            if (i1 < 0 || l[e] > l[i1]) i1 = e;
        }
        // softmax over the two selected logits
        float r  = expf(l[i1] - l[i0]);
        float w0 = 1.f / (1.f + r);
        float w1 = r / (1.f + r);

        int p0 = atomicAdd(&g_count[i0], 1);
        int s0 = i0 * CAP + p0;
        g_tok[s0] = t; g_pairpos[2 * t] = s0; g_pairw[2 * t] = w0;

        int p1 = atomicAdd(&g_count[i1], 1);
        int s1 = i1 * CAP + p1;
        g_tok[s1] = t; g_pairpos[2 * t + 1] = s1; g_pairw[2 * t + 1] = w1;
    }
}

// =================================================================
// Tiled fp32 GEMM: 128x128 tile, BK=16, 256 threads, 8x8 per thread.
// MODE 0: g1  = relu(x @ gw1 + gb1)                    K=DIN,  N=GHID
// MODE 1: H   = relu(x[tok] @ w1[e] + b1[e])           K=DIN,  N=HID
// MODE 2: MID = relu([H | x[tok]] @ [w2;wp] + b2+bp)   K=HID+DIN, N=HID
// MODE 3: PO  = MID @ w3[e] + b3[e]                    K=HID,  N=DOUT
// =================================================================
template <int MODE, int KDIM, int NDIM, bool RELU>
__global__ void __launch_bounds__(256) moe_gemm_kernel(
    const float* __restrict__ x,
    const float* __restrict__ Wa,
    const float* __restrict__ Wb,
    const float* __restrict__ ba,
    const float* __restrict__ bb) {

    __shared__ float As[16][128];
    __shared__ float Bs[16][128];

    const int e = (MODE == 0) ? 0 : (int)blockIdx.z;
    const int mcount = (MODE == 0) ? B_TOK : g_count[e];
    const int m0 = blockIdx.y * 128;
    if (m0 >= mcount) return;          // empty expert tile -> fast exit
    const int n0 = blockIdx.x * 128;
    const int tid = threadIdx.x;

    // A-tile load mapping: thread loads float4 at rows ra0/ra1, k-offset kv4
    const int ra0 = tid >> 2;          // 0..63
    const int ra1 = 64 + ra0;
    const int kv4 = (tid & 3) * 4;
    // B-tile load mapping
    const int kb0 = tid >> 5;          // 0..7
    const int kb1 = 8 + kb0;
    const int nv4 = (tid & 31) * 4;

    // expert-relative weight / bias pointers
    const float* W1e = Wa;
    const float* W2e = Wb;
    const float* b1e = ba;
    const float* b2e = bb;
    if (MODE == 1)      { W1e += (size_t)e * DIN * HID;  b1e += (size_t)e * HID; }
    else if (MODE == 2) { W1e += (size_t)e * HID * HID;  W2e += (size_t)e * DIN * HID;
                          b1e += (size_t)e * HID;        b2e += (size_t)e * HID; }
    else if (MODE == 3) { W1e += (size_t)e * HID * DOUT; b1e += (size_t)e * DOUT; }

    // A row base pointers (invalid rows read stale-but-finite data; their
    // results are never stored, and each output row depends only on its own
    // A row, so this is safe)
    const float* arow0; const float* arow1;
    const float* xrow0 = x; const float* xrow1 = x;
    if (MODE == 0) {
        arow0 = x + (size_t)(m0 + ra0) * DIN;
        arow1 = x + (size_t)(m0 + ra1) * DIN;
    } else if (MODE == 1) {
        arow0 = x + (size_t)g_tok[e * CAP + m0 + ra0] * DIN;
        arow1 = x + (size_t)g_tok[e * CAP + m0 + ra1] * DIN;
    } else if (MODE == 2) {
        xrow0 = x + (size_t)g_tok[e * CAP + m0 + ra0] * DIN;
        xrow1 = x + (size_t)g_tok[e * CAP + m0 + ra1] * DIN;
        arow0 = g_H + (size_t)(e * CAP + m0 + ra0) * HID;
        arow1 = g_H + (size_t)(e * CAP + m0 + ra1) * HID;
    } else {
        arow0 = g_MID + (size_t)(e * CAP + m0 + ra0) * HID;
        arow1 = g_MID + (size_t)(e * CAP + m0 + ra1) * HID;
    }

    float acc[8][8];
#pragma unroll
    for (int i = 0; i < 8; i++)
#pragma unroll
        for (int j = 0; j < 8; j++) acc[i][j] = 0.f;

    const int ty = tid >> 4;   // 0..15
    const int tx = tid & 15;   // 0..15

    auto loadA = [&](int kt, float4& A0, float4& A1) {
        if (MODE == 2 && kt >= HID) {
            int k = kt - HID + kv4;
            A0 = *(const float4*)(xrow0 + k);
            A1 = *(const float4*)(xrow1 + k);
        } else {
            int k = kt + kv4;
            A0 = *(const float4*)(arow0 + k);
            A1 = *(const float4*)(arow1 + k);
        }
    };
    auto loadB = [&](int kt, float4& B0, float4& B1) {
        const float* wsrc = W1e;
        int kloc = kt;
        if (MODE == 2 && kt >= HID) { wsrc = W2e; kloc = kt - HID; }
        B0 = *(const float4*)(wsrc + (size_t)(kloc + kb0) * NDIM + n0 + nv4);
        B1 = *(const float4*)(wsrc + (size_t)(kloc + kb1) * NDIM + n0 + nv4);
    };

    float4 aR0, aR1, bR0, bR1;
    loadA(0, aR0, aR1);
    loadB(0, bR0, bR1);

    for (int kt = 0; kt < KDIM; kt += 16) {
        // store prefetched tile to smem (A transposed)
        As[kv4 + 0][ra0] = aR0.x; As[kv4 + 1][ra0] = aR0.y;
        As[kv4 + 2][ra0] = aR0.z; As[kv4 + 3][ra0] = aR0.w;
        As[kv4 + 0][ra1] = aR1.x; As[kv4 + 1][ra1] = aR1.y;
        As[kv4 + 2][ra1] = aR1.z; As[kv4 + 3][ra1] = aR1.w;
        *(float4*)&Bs[kb0][nv4] = bR0;
        *(float4*)&Bs[kb1][nv4] = bR1;
        __syncthreads();

        if (kt + 16 < KDIM) {          // prefetch next tile (overlaps compute)
            loadA(kt + 16, aR0, aR1);
            loadB(kt + 16, bR0, bR1);
        }

#pragma unroll
        for (int kk = 0; kk < 16; kk++) {
            float a[8], b[8];
            *(float4*)&a[0] = *(const float4*)&As[kk][4 * ty];
            *(float4*)&a[4] = *(const float4*)&As[kk][64 + 4 * ty];
            *(float4*)&b[0] = *(const float4*)&Bs[kk][4 * tx];
            *(float4*)&b[4] = *(const float4*)&Bs[kk][64 + 4 * tx];
#pragma unroll
            for (int i = 0; i < 8; i++)
#pragma unroll
                for (int j = 0; j < 8; j++) acc[i][j] += a[i] * b[j];
        }
        __syncthreads();
    }

    // ---- epilogue: bias (+bias2 for MODE2), optional relu, store ----
    float bn[8];
    {
        float4 b0 = *(const float4*)&b1e[n0 + 4 * tx];
        float4 b1 = *(const float4*)&b1e[n0 + 64 + 4 * tx];
        bn[0] = b0.x; bn[1] = b0.y; bn[2] = b0.z; bn[3] = b0.w;
        bn[4] = b1.x; bn[5] = b1.y; bn[6] = b1.z; bn[7] = b1.w;
        if (MODE == 2) {
            float4 c0 = *(const float4*)&b2e[n0 + 4 * tx];
            float4 c1 = *(const float4*)&b2e[n0 + 64 + 4 * tx];
            bn[0] += c0.x; bn[1] += c0.y; bn[2] += c0.z; bn[3] += c0.w;
            bn[4] += c1.x; bn[5] += c1.y; bn[6] += c1.z; bn[7] += c1.w;
        }
    }

    float* Cb;
    if (MODE == 0)      Cb = g_g1;
    else if (MODE == 1) Cb = g_H  + (size_t)e * CAP * NDIM;
    else if (MODE == 2) Cb = g_MID + (size_t)e * CAP * NDIM;
    else                Cb = g_PO + (size_t)e * CAP * NDIM;

#pragma unroll
    for (int i = 0; i < 8; i++) {
        int m = m0 + ((i < 4) ? (4 * ty + i) : (64 + 4 * ty + (i - 4)));
        if (m >= mcount) continue;
        float* crow = Cb + (size_t)m * NDIM;
        float4 v0, v1;
        v0.x = acc[i][0] + bn[0]; v0.y = acc[i][1] + bn[1];
        v0.z = acc[i][2] + bn[2]; v0.w = acc[i][3] + bn[3];
        v1.x = acc[i][4] + bn[4]; v1.y = acc[i][5] + bn[5];
        v1.z = acc[i][6] + bn[6]; v1.w = acc[i][7] + bn[7];
        if (RELU) {
            v0.x = fmaxf(v0.x, 0.f); v0.y = fmaxf(v0.y, 0.f);
            v0.z = fmaxf(v0.z, 0.f); v0.w = fmaxf(v0.w, 0.f);
            v1.x = fmaxf(v1.x, 0.f); v1.y = fmaxf(v1.y, 0.f);
            v1.z = fmaxf(v1.z, 0.f); v1.w = fmaxf(v1.w, 0.f);
        }
        *(float4*)&crow[n0 + 4 * tx]      = v0;
        *(float4*)&crow[n0 + 64 + 4 * tx] = v1;
    }
}

// =================================================================
// Combine: out[t] = w0 * PO[p0] + w1 * PO[p1]  (deterministic; goes
// through recorded pair positions, no atomics on the output)
// =================================================================
__global__ void combine_kernel(float* __restrict__ out) {
    const int t = blockIdx.x;
    const int p0 = g_pairpos[2 * t], p1 = g_pairpos[2 * t + 1];
    const float w0 = g_pairw[2 * t], w1 = g_pairw[2 * t + 1];
    const float4* r0 = (const float4*)(g_PO + (size_t)p0 * DOUT);
    const float4* r1 = (const float4*)(g_PO + (size_t)p1 * DOUT);
    float4* o = (float4*)(out + (size_t)t * DOUT);
    for (int c = threadIdx.x; c < DOUT / 4; c += blockDim.x) {
        float4 a = r0[c], b = r1[c], v;
        v.x = w0 * a.x + w1 * b.x;
        v.y = w0 * a.y + w1 * b.y;
        v.z = w0 * a.z + w1 * b.z;
        v.w = w0 * a.w + w1 * b.w;
        o[c] = v;
    }
}

// =================================================================
// Launch
// =================================================================
extern "C" void kernel_launch(void* const* d_in, const int* in_sizes, int n_in,
                              void* d_out, int out_size) {
    (void)in_sizes; (void)n_in; (void)out_size;
    const float* x   = (const float*)d_in[0];
    const float* w1  = (const float*)d_in[1];
    const float* b1  = (const float*)d_in[2];
    const float* w2  = (const float*)d_in[3];
    const float* b2  = (const float*)d_in[4];
    const float* w3  = (const float*)d_in[5];
    const float* b3  = (const float*)d_in[6];
    const float* wp  = (const float*)d_in[7];
    const float* bp  = (const float*)d_in[8];
    const float* gw1 = (const float*)d_in[9];
    const float* gb1 = (const float*)d_in[10];
    const float* gw2 = (const float*)d_in[11];
    const float* gb2 = (const float*)d_in[12];
    float* out = (float*)d_out;

    reset_counts_kernel<<<1, 32>>>();

    // Gating GEMM: g1 = relu(x @ gw1 + gb1)
    {
        dim3 grid(GHID / 128, B_TOK / 128, 1);
        moe_gemm_kernel<0, DIN, GHID, true><<<grid, 256>>>(
            x, gw1, nullptr, gb1, nullptr);
    }

    // Top-2 + softmax + scatter
    gating_topk_scatter_kernel<<<B_TOK, 128>>>(gw2, gb2);

    // GEMM1: H = relu(x[tok] @ w1[e] + b1[e])
    {
        dim3 grid(HID / 128, CAP / 128, NEXP);
        moe_gemm_kernel<1, DIN, HID, true><<<grid, 256>>>(
            x, w1, nullptr, b1, nullptr);
    }

    // GEMM2 (fused wp): MID = relu([H | x] @ [w2; wp] + b2 + bp)
    {
        dim3 grid(HID / 128, CAP / 128, NEXP);
        moe_gemm_kernel<2, HID + DIN, HID, true><<<grid, 256>>>(
            x, w2, wp, b2, bp);
    }

    // GEMM3: PO = MID @ w3[e] + b3[e]
    {
        dim3 grid(DOUT / 128, CAP / 128, NEXP);
        moe_gemm_kernel<3, HID, DOUT, false><<<grid, 256>>>(
            x, w3, nullptr, b3, nullptr);
    }

    // Weighted combine into output
    combine_kernel<<<B_TOK, 256>>>(out);
}

// round 5
// speedup vs baseline: 1.9388x; 1.9388x over previous
#include <cuda_runtime.h>
#include <math.h>

// Problem constants (match reference)
#define B_TOK 8192
#define DIN   1024
#define HID   2048
#define DOUT  1024
#define NEXP  8
#define GHID  1024
#define CAP   8192   // worst-case tokens per expert

// -------- device scratch (static globals; allocation-free) --------
__device__ float g_g1[(size_t)B_TOK * GHID];          //  32 MB  gating hidden
__device__ float g_H  [(size_t)NEXP * CAP * HID];     // 512 MB  relu(x@w1+b1) per pair slot
__device__ float g_MID[(size_t)NEXP * CAP * HID];     // 512 MB  relu(h@w2 + x@wp + b2+bp)
__device__ float g_PO [(size_t)NEXP * CAP * DOUT];    // 256 MB  expert outputs per pair slot
__device__ int   g_count[NEXP];
__device__ int   g_tok[NEXP * CAP];                   // token id per pair slot
__device__ int   g_pairpos[B_TOK * 2];                // token -> its 2 pair slots
__device__ float g_pairw [B_TOK * 2];                 // token -> its 2 softmax weights

// =================================================================
// Reset per-expert counters (must run every graph replay)
// =================================================================
__global__ void reset_counts_kernel() {
    if (threadIdx.x < NEXP) g_count[threadIdx.x] = 0;
}

// =================================================================
// Gating epilogue: logits = relu_g1 @ gw2 + gb2 ; top-2 ; softmax ;
// scatter. FP32 throughout — expert SELECTION must match reference
// exactly (a flipped near-tie would cost ~1e-2 global rel err).
// =================================================================
__global__ void gating_topk_scatter_kernel(const float* __restrict__ gw2,
                                           const float* __restrict__ gb2) {
    const int t   = blockIdx.x;
    const int tid = threadIdx.x;

    float acc[NEXP];
#pragma unroll
    for (int e = 0; e < NEXP; e++) acc[e] = 0.f;

    const float* row = g_g1 + (size_t)t * GHID;
    for (int k = tid; k < GHID; k += 128) {
        float v = row[k];
        const float* w = gw2 + (size_t)k * NEXP;
#pragma unroll
        for (int e = 0; e < NEXP; e++) acc[e] += v * w[e];
    }

    __shared__ float sm[128 * NEXP];
#pragma unroll
    for (int e = 0; e < NEXP; e++) sm[tid * NEXP + e] = acc[e];
    __syncthreads();
    for (int s = 64; s > 0; s >>= 1) {
        if (tid < s) {
#pragma unroll
            for (int e = 0; e < NEXP; e++)
                sm[tid * NEXP + e] += sm[(tid + s) * NEXP + e];
        }
        __syncthreads();
    }

    if (tid == 0) {
        float l[NEXP];
#pragma unroll
        for (int e = 0; e < NEXP; e++) l[e] = sm[e] + gb2[e];

        int i0 = 0;
#pragma unroll
        for (int e = 1; e < NEXP; e++) if (l[e] > l[i0]) i0 = e;
        int i1 = -1;
#pragma unroll
        for (int e = 0; e < NEXP; e++) {
            if (e == i0) continue;
            if (i1 < 0 || l[e] > l[i1]) i1 = e;
        }
        float r  = expf(l[i1] - l[i0]);
        float w0 = 1.f / (1.f + r);
        float w1 = r / (1.f + r);

        int p0 = atomicAdd(&g_count[i0], 1);
        int s0 = i0 * CAP + p0;
        g_tok[s0] = t; g_pairpos[2 * t] = s0; g_pairw[2 * t] = w0;

        int p1 = atomicAdd(&g_count[i1], 1);
        int s1 = i1 * CAP + p1;
        g_tok[s1] = t; g_pairpos[2 * t + 1] = s1; g_pairw[2 * t + 1] = w1;
    }
}

// =================================================================
// FP32 gating GEMM (exact): g1 = relu(x @ gw1 + gb1)
// 128x128 tile, BK=16, 256 threads, 8x8 per thread.
// =================================================================
__global__ void __launch_bounds__(256) gating_gemm_kernel(
    const float* __restrict__ x,
    const float* __restrict__ W,
    const float* __restrict__ bias) {

    __shared__ float As[16][128];
    __shared__ float Bs[16][128];

    const int m0 = blockIdx.y * 128;
    const int n0 = blockIdx.x * 128;
    const int tid = threadIdx.x;

    const int ra0 = tid >> 2;
    const int ra1 = 64 + ra0;
    const int kv4 = (tid & 3) * 4;
    const int kb0 = tid >> 5;
    const int kb1 = 8 + kb0;
    const int nv4 = (tid & 31) * 4;

    const float* arow0 = x + (size_t)(m0 + ra0) * DIN;
    const float* arow1 = x + (size_t)(m0 + ra1) * DIN;

    float acc[8][8];
#pragma unroll
    for (int i = 0; i < 8; i++)
#pragma unroll
        for (int j = 0; j < 8; j++) acc[i][j] = 0.f;

    const int ty = tid >> 4;
    const int tx = tid & 15;

    float4 aR0 = *(const float4*)(arow0 + kv4);
    float4 aR1 = *(const float4*)(arow1 + kv4);
    float4 bR0 = *(const float4*)(W + (size_t)kb0 * GHID + n0 + nv4);
    float4 bR1 = *(const float4*)(W + (size_t)kb1 * GHID + n0 + nv4);

    for (int kt = 0; kt < DIN; kt += 16) {
        As[kv4 + 0][ra0] = aR0.x; As[kv4 + 1][ra0] = aR0.y;
        As[kv4 + 2][ra0] = aR0.z; As[kv4 + 3][ra0] = aR0.w;
        As[kv4 + 0][ra1] = aR1.x; As[kv4 + 1][ra1] = aR1.y;
        As[kv4 + 2][ra1] = aR1.z; As[kv4 + 3][ra1] = aR1.w;
        *(float4*)&Bs[kb0][nv4] = bR0;
        *(float4*)&Bs[kb1][nv4] = bR1;
        __syncthreads();

        if (kt + 16 < DIN) {
            aR0 = *(const float4*)(arow0 + kt + 16 + kv4);
            aR1 = *(const float4*)(arow1 + kt + 16 + kv4);
            bR0 = *(const float4*)(W + (size_t)(kt + 16 + kb0) * GHID + n0 + nv4);
            bR1 = *(const float4*)(W + (size_t)(kt + 16 + kb1) * GHID + n0 + nv4);
        }

#pragma unroll
        for (int kk = 0; kk < 16; kk++) {
            float a[8], b[8];
            *(float4*)&a[0] = *(const float4*)&As[kk][4 * ty];
            *(float4*)&a[4] = *(const float4*)&As[kk][64 + 4 * ty];
            *(float4*)&b[0] = *(const float4*)&Bs[kk][4 * tx];
            *(float4*)&b[4] = *(const float4*)&Bs[kk][64 + 4 * tx];
#pragma unroll
            for (int i = 0; i < 8; i++)
#pragma unroll
                for (int j = 0; j < 8; j++) acc[i][j] += a[i] * b[j];
        }
        __syncthreads();
    }

    float bn[8];
    {
        float4 b0 = *(const float4*)&bias[n0 + 4 * tx];
        float4 b1 = *(const float4*)&bias[n0 + 64 + 4 * tx];
        bn[0] = b0.x; bn[1] = b0.y; bn[2] = b0.z; bn[3] = b0.w;
        bn[4] = b1.x; bn[5] = b1.y; bn[6] = b1.z; bn[7] = b1.w;
    }

#pragma unroll
    for (int i = 0; i < 8; i++) {
        int m = m0 + ((i < 4) ? (4 * ty + i) : (64 + 4 * ty + (i - 4)));
        float* crow = g_g1 + (size_t)m * GHID;
        float4 v0, v1;
        v0.x = fmaxf(acc[i][0] + bn[0], 0.f); v0.y = fmaxf(acc[i][1] + bn[1], 0.f);
        v0.z = fmaxf(acc[i][2] + bn[2], 0.f); v0.w = fmaxf(acc[i][3] + bn[3], 0.f);
        v1.x = fmaxf(acc[i][4] + bn[4], 0.f); v1.y = fmaxf(acc[i][5] + bn[5], 0.f);
        v1.z = fmaxf(acc[i][6] + bn[6], 0.f); v1.w = fmaxf(acc[i][7] + bn[7], 0.f);
        *(float4*)&crow[n0 + 4 * tx]      = v0;
        *(float4*)&crow[n0 + 64 + 4 * tx] = v1;
    }
}

// =================================================================
// TF32 tensor-core grouped GEMM (expert GEMMs).
// 128x128 tile, BK=16, 256 threads = 8 warps in 2(m) x 4(n) grid.
// Each warp: 64x32 via 4x4 fragments of mma.sync m16n8k8 tf32.
// MODE 1: H   = relu(x[tok] @ w1[e] + b1[e])           K=DIN
// MODE 2: MID = relu([H | x[tok]] @ [w2;wp] + b2+bp)   K=HID+DIN
// MODE 3: PO  = MID @ w3[e] + b3[e]                    K=HID
// =================================================================
__device__ __forceinline__ unsigned f2tf(float f) {
    unsigned u;
    asm("cvt.rna.tf32.f32 %0, %1;" : "=r"(u) : "f"(f));
    return u;
}

#define MMA_TF32(d, a, b)                                                    \
    asm volatile(                                                            \
        "mma.sync.aligned.m16n8k8.row.col.f32.tf32.tf32.f32 "                \
        "{%0,%1,%2,%3}, {%4,%5,%6,%7}, {%8,%9}, {%0,%1,%2,%3};\n"            \
        : "+f"((d)[0]), "+f"((d)[1]), "+f"((d)[2]), "+f"((d)[3])             \
        : "r"((a)[0]), "r"((a)[1]), "r"((a)[2]), "r"((a)[3]),                \
          "r"((b)[0]), "r"((b)[1]))

#define SMLD 136   // smem row stride in floats: bank = 8*k + m -> conflict-free

template <int MODE, int KDIM, int NDIM, bool RELU>
__global__ void __launch_bounds__(256, 1) moe_mma_kernel(
    const float* __restrict__ x,
    const float* __restrict__ Wa,
    const float* __restrict__ Wb,
    const float* __restrict__ ba,
    const float* __restrict__ bb) {

    __shared__ unsigned As[16][SMLD];
    __shared__ unsigned Bs[16][SMLD];

    const int e = (int)blockIdx.z;
    const int mcount = g_count[e];
    const int m0 = blockIdx.y * 128;
    if (m0 >= mcount) return;
    const int n0 = blockIdx.x * 128;
    const int tid  = threadIdx.x;
    const int lane = tid & 31;
    const int warp = tid >> 5;
    const int wm = (warp & 1) * 64;   // warp m-offset within tile
    const int wn = (warp >> 1) * 32;  // warp n-offset within tile
    const int group = lane >> 2;      // 0..7
    const int tl    = lane & 3;       // 0..3

    // global->smem load mapping (same as fp32 version)
    const int ra0 = tid >> 2;
    const int ra1 = 64 + ra0;
    const int kv4 = (tid & 3) * 4;
    const int kb0 = tid >> 5;
    const int kb1 = 8 + kb0;
    const int nv4 = (tid & 31) * 4;

    // expert weight/bias pointers
    const float* W1e = Wa;
    const float* W2e = Wb;
    const float* b1e = ba;
    const float* b2e = bb;
    if (MODE == 1)      { W1e += (size_t)e * DIN * HID;  b1e += (size_t)e * HID; }
    else if (MODE == 2) { W1e += (size_t)e * HID * HID;  W2e += (size_t)e * DIN * HID;
                          b1e += (size_t)e * HID;        b2e += (size_t)e * HID; }
    else                { W1e += (size_t)e * HID * DOUT; b1e += (size_t)e * DOUT; }

    // A row base pointers (invalid rows read stale-but-finite slot 0 data;
    // their results are never stored)
    const float* arow0; const float* arow1;
    const float* xrow0 = x; const float* xrow1 = x;
    if (MODE == 1) {
        arow0 = x + (size_t)g_tok[e * CAP + m0 + ra0] * DIN;
        arow1 = x + (size_t)g_tok[e * CAP + m0 + ra1] * DIN;
    } else if (MODE == 2) {
        xrow0 = x + (size_t)g_tok[e * CAP + m0 + ra0] * DIN;
        xrow1 = x + (size_t)g_tok[e * CAP + m0 + ra1] * DIN;
        arow0 = g_H + (size_t)(e * CAP + m0 + ra0) * HID;
        arow1 = g_H + (size_t)(e * CAP + m0 + ra1) * HID;
    } else {
        arow0 = g_MID + (size_t)(e * CAP + m0 + ra0) * HID;
        arow1 = g_MID + (size_t)(e * CAP + m0 + ra1) * HID;
    }

    float acc[4][4][4];
#pragma unroll
    for (int mi = 0; mi < 4; mi++)
#pragma unroll
        for (int ni = 0; ni < 4; ni++)
#pragma unroll
            for (int r = 0; r < 4; r++) acc[mi][ni][r] = 0.f;

    auto loadA = [&](int kt, float4& A0, float4& A1) {
        if (MODE == 2 && kt >= HID) {
            int k = kt - HID + kv4;
            A0 = *(const float4*)(xrow0 + k);
            A1 = *(const float4*)(xrow1 + k);
        } else {
            int k = kt + kv4;
            A0 = *(const float4*)(arow0 + k);
            A1 = *(const float4*)(arow1 + k);
        }
    };
    auto loadB = [&](int kt, float4& B0, float4& B1) {
        const float* wsrc = W1e;
        int kloc = kt;
        if (MODE == 2 && kt >= HID) { wsrc = W2e; kloc = kt - HID; }
        B0 = *(const float4*)(wsrc + (size_t)(kloc + kb0) * NDIM + n0 + nv4);
        B1 = *(const float4*)(wsrc + (size_t)(kloc + kb1) * NDIM + n0 + nv4);
    };

    float4 aR0, aR1, bR0, bR1;
    loadA(0, aR0, aR1);
    loadB(0, bR0, bR1);

    for (int kt = 0; kt < KDIM; kt += 16) {
        // store current chunk to smem (tf32-rounded); A stored [k][m]
        As[kv4 + 0][ra0] = f2tf(aR0.x); As[kv4 + 1][ra0] = f2tf(aR0.y);
        As[kv4 + 2][ra0] = f2tf(aR0.z); As[kv4 + 3][ra0] = f2tf(aR0.w);
        As[kv4 + 0][ra1] = f2tf(aR1.x); As[kv4 + 1][ra1] = f2tf(aR1.y);
        As[kv4 + 2][ra1] = f2tf(aR1.z); As[kv4 + 3][ra1] = f2tf(aR1.w);
        {
            uint4 u0 = make_uint4(f2tf(bR0.x), f2tf(bR0.y), f2tf(bR0.z), f2tf(bR0.w));
            uint4 u1 = make_uint4(f2tf(bR1.x), f2tf(bR1.y), f2tf(bR1.z), f2tf(bR1.w));
            *(uint4*)&Bs[kb0][nv4] = u0;
            *(uint4*)&Bs[kb1][nv4] = u1;
        }
        __syncthreads();

        if (kt + 16 < KDIM) {   // prefetch next chunk into regs
            loadA(kt + 16, aR0, aR1);
            loadB(kt + 16, bR0, bR1);
        }

#pragma unroll
        for (int ks = 0; ks < 16; ks += 8) {
            unsigned a[4][4], b[4][2];
#pragma unroll
            for (int mi = 0; mi < 4; mi++) {
                int mb = wm + mi * 16 + group;
                a[mi][0] = As[ks + tl][mb];
                a[mi][1] = As[ks + tl][mb + 8];
                a[mi][2] = As[ks + tl + 4][mb];
                a[mi][3] = As[ks + tl + 4][mb + 8];
            }
#pragma unroll
            for (int ni = 0; ni < 4; ni++) {
                int nb = wn + ni * 8 + group;
                b[ni][0] = Bs[ks + tl][nb];
                b[ni][1] = Bs[ks + tl + 4][nb];
            }
#pragma unroll
            for (int mi = 0; mi < 4; mi++)
#pragma unroll
                for (int ni = 0; ni < 4; ni++)
                    MMA_TF32(acc[mi][ni], a[mi], b[ni]);
        }
        __syncthreads();
    }

    // ---- epilogue: per-column bias (float2), optional relu, fragment store
    float2 bn[4];
#pragma unroll
    for (int ni = 0; ni < 4; ni++) {
        int c = n0 + wn + ni * 8 + tl * 2;
        bn[ni] = *(const float2*)&b1e[c];
        if (MODE == 2) {
            float2 c2 = *(const float2*)&b2e[c];
            bn[ni].x += c2.x; bn[ni].y += c2.y;
        }
    }

    float* Cb;
    if (MODE == 1)      Cb = g_H   + (size_t)e * CAP * NDIM;
    else if (MODE == 2) Cb = g_MID + (size_t)e * CAP * NDIM;
    else                Cb = g_PO  + (size_t)e * CAP * NDIM;

#pragma unroll
    for (int mi = 0; mi < 4; mi++) {
        int r0 = m0 + wm + mi * 16 + group;
        int r1 = r0 + 8;
        float* crow0 = Cb + (size_t)r0 * NDIM;
        float* crow1 = Cb + (size_t)r1 * NDIM;
#pragma unroll
        for (int ni = 0; ni < 4; ni++) {
            int c = n0 + wn + ni * 8 + tl * 2;
            float2 v0, v1;
            v0.x = acc[mi][ni][0] + bn[ni].x;
            v0.y = acc[mi][ni][1] + bn[ni].y;
            v1.x = acc[mi][ni][2] + bn[ni].x;
            v1.y = acc[mi][ni][3] + bn[ni].y;
            if (RELU) {
                v0.x = fmaxf(v0.x, 0.f); v0.y = fmaxf(v0.y, 0.f);
                v1.x = fmaxf(v1.x, 0.f); v1.y = fmaxf(v1.y, 0.f);
            }
            if (r0 < mcount) *(float2*)&crow0[c] = v0;
            if (r1 < mcount) *(float2*)&crow1[c] = v1;
        }
    }
}

// =================================================================
// Combine: out[t] = w0 * PO[p0] + w1 * PO[p1]  (deterministic)
// =================================================================
__global__ void combine_kernel(float* __restrict__ out) {
    const int t = blockIdx.x;
    const int p0 = g_pairpos[2 * t], p1 = g_pairpos[2 * t + 1];
    const float w0 = g_pairw[2 * t], w1 = g_pairw[2 * t + 1];
    const float4* r0 = (const float4*)(g_PO + (size_t)p0 * DOUT);
    const float4* r1 = (const float4*)(g_PO + (size_t)p1 * DOUT);
    float4* o = (float4*)(out + (size_t)t * DOUT);
    for (int c = threadIdx.x; c < DOUT / 4; c += blockDim.x) {
        float4 a = r0[c], b = r1[c], v;
        v.x = w0 * a.x + w1 * b.x;
        v.y = w0 * a.y + w1 * b.y;
        v.z = w0 * a.z + w1 * b.z;
        v.w = w0 * a.w + w1 * b.w;
        o[c] = v;
    }
}

// =================================================================
// Launch
// =================================================================
extern "C" void kernel_launch(void* const* d_in, const int* in_sizes, int n_in,
                              void* d_out, int out_size) {
    (void)in_sizes; (void)n_in; (void)out_size;
    const float* x   = (const float*)d_in[0];
    const float* w1  = (const float*)d_in[1];
    const float* b1  = (const float*)d_in[2];
    const float* w2  = (const float*)d_in[3];
    const float* b2  = (const float*)d_in[4];
    const float* w3  = (const float*)d_in[5];
    const float* b3  = (const float*)d_in[6];
    const float* wp  = (const float*)d_in[7];
    const float* bp  = (const float*)d_in[8];
    const float* gw1 = (const float*)d_in[9];
    const float* gb1 = (const float*)d_in[10];
    const float* gw2 = (const float*)d_in[11];
    const float* gb2 = (const float*)d_in[12];
    float* out = (float*)d_out;

    reset_counts_kernel<<<1, 32>>>();

    // Gating GEMM (exact fp32): g1 = relu(x @ gw1 + gb1)
    {
        dim3 grid(GHID / 128, B_TOK / 128, 1);
        gating_gemm_kernel<<<grid, 256>>>(x, gw1, gb1);
    }

    // Top-2 + softmax + scatter
    gating_topk_scatter_kernel<<<B_TOK, 128>>>(gw2, gb2);

    // GEMM1 (tf32): H = relu(x[tok] @ w1[e] + b1[e])
    {
        dim3 grid(HID / 128, CAP / 128, NEXP);
        moe_mma_kernel<1, DIN, HID, true><<<grid, 256>>>(
            x, w1, nullptr, b1, nullptr);
    }

    // GEMM2 (tf32, fused wp): MID = relu([H | x] @ [w2; wp] + b2 + bp)
    {
        dim3 grid(HID / 128, CAP / 128, NEXP);
        moe_mma_kernel<2, HID + DIN, HID, true><<<grid, 256>>>(
            x, w2, wp, b2, bp);
    }

    // GEMM3 (tf32): PO = MID @ w3[e] + b3[e]
    {
        dim3 grid(DOUT / 128, CAP / 128, NEXP);
        moe_mma_kernel<3, HID, DOUT, false><<<grid, 256>>>(
            x, w3, nullptr, b3, nullptr);
    }

    // Weighted combine into output
    combine_kernel<<<B_TOK, 256>>>(out);
}

// round 7
// speedup vs baseline: 1.9941x; 1.0285x over previous
#include <cuda_runtime.h>
#include <math.h>

// Problem constants (match reference)
#define B_TOK 8192
#define DIN   1024
#define HID   2048
#define DOUT  1024
#define NEXP  8
#define GHID  1024
#define CAP   8192   // worst-case tokens per expert

// -------- device scratch (static globals; allocation-free) --------
__device__ float g_g1[(size_t)B_TOK * GHID];          //  32 MB  gating hidden
__device__ float g_H  [(size_t)NEXP * CAP * HID];     // 512 MB  relu(x@w1+b1)
__device__ float g_MID[(size_t)NEXP * CAP * HID];     // 512 MB  relu(h@w2 + x@wp + b)
__device__ float g_PO [(size_t)NEXP * CAP * DOUT];    // 256 MB  expert outputs
__device__ int   g_count[NEXP];
__device__ int   g_tok[NEXP * CAP];
__device__ int   g_pairpos[B_TOK * 2];
__device__ float g_pairw [B_TOK * 2];

__device__ __forceinline__ unsigned f2tf(float f) {
    unsigned u;
    asm("cvt.rna.tf32.f32 %0, %1;" : "=r"(u) : "f"(f));
    return u;
}

// =================================================================
// Reset per-expert counters (must run every graph replay)
// =================================================================
__global__ void reset_counts_kernel() {
    if (threadIdx.x < NEXP) g_count[threadIdx.x] = 0;
}

// =================================================================
// Gating epilogue: logits = relu_g1 @ gw2 + gb2 ; top-2 ; softmax ;
// scatter. FP32 throughout — selection must match reference exactly.
// =================================================================
__global__ void gating_topk_scatter_kernel(const float* __restrict__ gw2,
                                           const float* __restrict__ gb2) {
    const int t   = blockIdx.x;
    const int tid = threadIdx.x;

    float acc[NEXP];
#pragma unroll
    for (int e = 0; e < NEXP; e++) acc[e] = 0.f;

    const float* row = g_g1 + (size_t)t * GHID;
    for (int k = tid; k < GHID; k += 128) {
        float v = row[k];
        const float* w = gw2 + (size_t)k * NEXP;
#pragma unroll
        for (int e = 0; e < NEXP; e++) acc[e] += v * w[e];
    }

    __shared__ float sm[128 * NEXP];
#pragma unroll
    for (int e = 0; e < NEXP; e++) sm[tid * NEXP + e] = acc[e];
    __syncthreads();
    for (int s = 64; s > 0; s >>= 1) {
        if (tid < s) {
#pragma unroll
            for (int e = 0; e < NEXP; e++)
                sm[tid * NEXP + e] += sm[(tid + s) * NEXP + e];
        }
        __syncthreads();
    }

    if (tid == 0) {
        float l[NEXP];
#pragma unroll
        for (int e = 0; e < NEXP; e++) l[e] = sm[e] + gb2[e];

        int i0 = 0;
#pragma unroll
        for (int e = 1; e < NEXP; e++) if (l[e] > l[i0]) i0 = e;
        int i1 = -1;
#pragma unroll
        for (int e = 0; e < NEXP; e++) {
            if (e == i0) continue;
            if (i1 < 0 || l[e] > l[i1]) i1 = e;
        }
        float r  = expf(l[i1] - l[i0]);
        float w0 = 1.f / (1.f + r);
        float w1 = r / (1.f + r);

        int p0 = atomicAdd(&g_count[i0], 1);
        int s0 = i0 * CAP + p0;
        g_tok[s0] = t; g_pairpos[2 * t] = s0; g_pairw[2 * t] = w0;

        int p1 = atomicAdd(&g_count[i1], 1);
        int s1 = i1 * CAP + p1;
        g_tok[s1] = t; g_pairpos[2 * t + 1] = s1; g_pairw[2 * t + 1] = w1;
    }
}

// =================================================================
// FP32 gating GEMM (exact): g1 = relu(x @ gw1 + gb1)
// =================================================================
__global__ void __launch_bounds__(256) gating_gemm_kernel(
    const float* __restrict__ x,
    const float* __restrict__ W,
    const float* __restrict__ bias) {

    __shared__ float As[16][128];
    __shared__ float Bs[16][128];

    const int m0 = blockIdx.y * 128;
    const int n0 = blockIdx.x * 128;
    const int tid = threadIdx.x;

    const int ra0 = tid >> 2;
    const int ra1 = 64 + ra0;
    const int kv4 = (tid & 3) * 4;
    const int kb0 = tid >> 5;
    const int kb1 = 8 + kb0;
    const int nv4 = (tid & 31) * 4;

    const float* arow0 = x + (size_t)(m0 + ra0) * DIN;
    const float* arow1 = x + (size_t)(m0 + ra1) * DIN;

    float acc[8][8];
#pragma unroll
    for (int i = 0; i < 8; i++)
#pragma unroll
        for (int j = 0; j < 8; j++) acc[i][j] = 0.f;

    const int ty = tid >> 4;
    const int tx = tid & 15;

    float4 aR0 = *(const float4*)(arow0 + kv4);
    float4 aR1 = *(const float4*)(arow1 + kv4);
    float4 bR0 = *(const float4*)(W + (size_t)kb0 * GHID + n0 + nv4);
    float4 bR1 = *(const float4*)(W + (size_t)kb1 * GHID + n0 + nv4);

    for (int kt = 0; kt < DIN; kt += 16) {
        As[kv4 + 0][ra0] = aR0.x; As[kv4 + 1][ra0] = aR0.y;
        As[kv4 + 2][ra0] = aR0.z; As[kv4 + 3][ra0] = aR0.w;
        As[kv4 + 0][ra1] = aR1.x; As[kv4 + 1][ra1] = aR1.y;
        As[kv4 + 2][ra1] = aR1.z; As[kv4 + 3][ra1] = aR1.w;
        *(float4*)&Bs[kb0][nv4] = bR0;
        *(float4*)&Bs[kb1][nv4] = bR1;
        __syncthreads();

        if (kt + 16 < DIN) {
            aR0 = *(const float4*)(arow0 + kt + 16 + kv4);
            aR1 = *(const float4*)(arow1 + kt + 16 + kv4);
            bR0 = *(const float4*)(W + (size_t)(kt + 16 + kb0) * GHID + n0 + nv4);
            bR1 = *(const float4*)(W + (size_t)(kt + 16 + kb1) * GHID + n0 + nv4);
        }

#pragma unroll
        for (int kk = 0; kk < 16; kk++) {
            float a[8], b[8];
            *(float4*)&a[0] = *(const float4*)&As[kk][4 * ty];
            *(float4*)&a[4] = *(const float4*)&As[kk][64 + 4 * ty];
            *(float4*)&b[0] = *(const float4*)&Bs[kk][4 * tx];
            *(float4*)&b[4] = *(const float4*)&Bs[kk][64 + 4 * tx];
#pragma unroll
            for (int i = 0; i < 8; i++)
#pragma unroll
                for (int j = 0; j < 8; j++) acc[i][j] += a[i] * b[j];
        }
        __syncthreads();
    }

    float bn[8];
    {
        float4 b0 = *(const float4*)&bias[n0 + 4 * tx];
        float4 b1 = *(const float4*)&bias[n0 + 64 + 4 * tx];
        bn[0] = b0.x; bn[1] = b0.y; bn[2] = b0.z; bn[3] = b0.w;
        bn[4] = b1.x; bn[5] = b1.y; bn[6] = b1.z; bn[7] = b1.w;
    }

#pragma unroll
    for (int i = 0; i < 8; i++) {
        int m = m0 + ((i < 4) ? (4 * ty + i) : (64 + 4 * ty + (i - 4)));
        float* crow = g_g1 + (size_t)m * GHID;
        float4 v0, v1;
        v0.x = fmaxf(acc[i][0] + bn[0], 0.f); v0.y = fmaxf(acc[i][1] + bn[1], 0.f);
        v0.z = fmaxf(acc[i][2] + bn[2], 0.f); v0.w = fmaxf(acc[i][3] + bn[3], 0.f);
        v1.x = fmaxf(acc[i][4] + bn[4], 0.f); v1.y = fmaxf(acc[i][5] + bn[5], 0.f);
        v1.z = fmaxf(acc[i][6] + bn[6], 0.f); v1.w = fmaxf(acc[i][7] + bn[7], 0.f);
        *(float4*)&crow[n0 + 4 * tx]      = v0;
        *(float4*)&crow[n0 + 64 + 4 * tx] = v1;
    }
}

// =================================================================
// TF32 tensor-core grouped GEMM, double-buffered smem.
// 128x128 tile, BK=16, 8 warps (2m x 4n), warp = 64x32 via 4x4
// m16n8k8 fragments. A in smem [m][k] stride 20 (vectorized stores,
// conflict-free fragment reads); B [k][n] stride 136 (both
// conflict-free). cvt.rna.tf32 applied on the smem-store path
// (identical numerics to the passing Round-5 build).
// MODE 1: H   = relu(x[tok] @ w1[e] + b1[e])           K=DIN
// MODE 2: MID = relu([H | x[tok]] @ [w2;wp] + b2+bp)   K=HID+DIN
// MODE 3: PO  = MID @ w3[e] + b3[e]                    K=HID
// =================================================================
#define MMA_TF32(d, a, b)                                                    \
    asm volatile(                                                            \
        "mma.sync.aligned.m16n8k8.row.col.f32.tf32.tf32.f32 "                \
        "{%0,%1,%2,%3}, {%4,%5,%6,%7}, {%8,%9}, {%0,%1,%2,%3};\n"            \
        : "+f"((d)[0]), "+f"((d)[1]), "+f"((d)[2]), "+f"((d)[3])             \
        : "r"((a)[0]), "r"((a)[1]), "r"((a)[2]), "r"((a)[3]),                \
          "r"((b)[0]), "r"((b)[1]))

#define A_ST 20    // A smem stride (floats): reads hit 32 distinct banks
#define B_ST 136   // B smem stride (floats): reads/stores conflict-free

template <int MODE, int KDIM, int NDIM, bool RELU>
__global__ void __launch_bounds__(256, 1) moe_mma_kernel(
    const float* __restrict__ x,
    const float* __restrict__ Wa,
    const float* __restrict__ Wb,
    const float* __restrict__ ba,
    const float* __restrict__ bb) {

    __shared__ unsigned As[2][128 * A_ST];   // [stage][m][k]
    __shared__ unsigned Bs[2][16 * B_ST];    // [stage][k][n]

    const int e = (int)blockIdx.z;
    const int mcount = g_count[e];
    const int m0 = blockIdx.y * 128;
    if (m0 >= mcount) return;
    const int n0 = blockIdx.x * 128;
    const int tid  = threadIdx.x;
    const int lane = tid & 31;
    const int warp = tid >> 5;
    const int wm = (warp & 1) * 64;
    const int wn = (warp >> 1) * 32;
    const int group = lane >> 2;
    const int tl    = lane & 3;

    // global->smem load mapping
    const int ra0 = tid >> 2;          // A rows ra0 and ra0+64
    const int kv4 = (tid & 3) * 4;
    const int kb0 = tid >> 5;          // B k-rows kb0 and kb0+8
    const int nv4 = (tid & 31) * 4;

    // expert weight/bias pointers
    const float* W1e = Wa;
    const float* W2e = Wb;
    const float* b1e = ba;
    const float* b2e = bb;
    if (MODE == 1)      { W1e += (size_t)e * DIN * HID;  b1e += (size_t)e * HID; }
    else if (MODE == 2) { W1e += (size_t)e * HID * HID;  W2e += (size_t)e * DIN * HID;
                          b1e += (size_t)e * HID;        b2e += (size_t)e * HID; }
    else                { W1e += (size_t)e * HID * DOUT; b1e += (size_t)e * DOUT; }

    // A row base pointers (rows >= mcount read valid stale slots; never stored)
    const float* arow0; const float* arow1;
    const float* xrow0 = x; const float* xrow1 = x;
    if (MODE == 1) {
        arow0 = x + (size_t)g_tok[e * CAP + m0 + ra0] * DIN;
        arow1 = x + (size_t)g_tok[e * CAP + m0 + 64 + ra0] * DIN;
    } else if (MODE == 2) {
        xrow0 = x + (size_t)g_tok[e * CAP + m0 + ra0] * DIN;
        xrow1 = x + (size_t)g_tok[e * CAP + m0 + 64 + ra0] * DIN;
        arow0 = g_H + (size_t)(e * CAP + m0 + ra0) * HID;
        arow1 = g_H + (size_t)(e * CAP + m0 + 64 + ra0) * HID;
    } else {
        arow0 = g_MID + (size_t)(e * CAP + m0 + ra0) * HID;
        arow1 = g_MID + (size_t)(e * CAP + m0 + 64 + ra0) * HID;
    }

    auto loadA = [&](int kt, float4& A0, float4& A1) {
        if (MODE == 2 && kt >= HID) {
            int k = kt - HID + kv4;
            A0 = *(const float4*)(xrow0 + k);
            A1 = *(const float4*)(xrow1 + k);
        } else {
            int k = kt + kv4;
            A0 = *(const float4*)(arow0 + k);
            A1 = *(const float4*)(arow1 + k);
        }
    };
    auto loadB = [&](int kt, float4& B0, float4& B1) {
        const float* wsrc = W1e;
        int kloc = kt;
        if (MODE == 2 && kt >= HID) { wsrc = W2e; kloc = kt - HID; }
        B0 = *(const float4*)(wsrc + (size_t)(kloc + kb0) * NDIM + n0 + nv4);
        B1 = *(const float4*)(wsrc + (size_t)(kloc + kb0 + 8) * NDIM + n0 + nv4);
    };

    auto store_stage = [&](int s, const float4& A0, const float4& A1,
                                  const float4& B0, const float4& B1) {
        uint4 u;
        u = make_uint4(f2tf(A0.x), f2tf(A0.y), f2tf(A0.z), f2tf(A0.w));
        *(uint4*)&As[s][ra0 * A_ST + kv4] = u;
        u = make_uint4(f2tf(A1.x), f2tf(A1.y), f2tf(A1.z), f2tf(A1.w));
        *(uint4*)&As[s][(64 + ra0) * A_ST + kv4] = u;
        u = make_uint4(f2tf(B0.x), f2tf(B0.y), f2tf(B0.z), f2tf(B0.w));
        *(uint4*)&Bs[s][kb0 * B_ST + nv4] = u;
        u = make_uint4(f2tf(B1.x), f2tf(B1.y), f2tf(B1.z), f2tf(B1.w));
        *(uint4*)&Bs[s][(8 + kb0) * B_ST + nv4] = u;
    };

    float acc[4][4][4];
#pragma unroll
    for (int mi = 0; mi < 4; mi++)
#pragma unroll
        for (int ni = 0; ni < 4; ni++)
#pragma unroll
            for (int r = 0; r < 4; r++) acc[mi][ni][r] = 0.f;

    float4 aR0, aR1, bR0, bR1;
    loadA(0, aR0, aR1);
    loadB(0, bR0, bR1);
    store_stage(0, aR0, aR1, bR0, bR1);
    __syncthreads();

    const int NCH = KDIM / 16;
#pragma unroll 1
    for (int c = 0; c < NCH; c++) {
        if (c + 1 < NCH) {              // issue next chunk's global loads
            loadA((c + 1) * 16, aR0, aR1);
            loadB((c + 1) * 16, bR0, bR1);
        }

        const unsigned* Au = As[c & 1];
        const unsigned* Bu = Bs[c & 1];
#pragma unroll
        for (int ks = 0; ks < 16; ks += 8) {
            unsigned a[4][4], b[4][2];
#pragma unroll
            for (int mi = 0; mi < 4; mi++) {
                const unsigned* r0 = Au + (wm + mi * 16 + group) * A_ST + ks + tl;
                a[mi][0] = r0[0];
                a[mi][2] = r0[4];
                a[mi][1] = r0[8 * A_ST];
                a[mi][3] = r0[8 * A_ST + 4];
            }
#pragma unroll
            for (int ni = 0; ni < 4; ni++) {
                int nb = wn + ni * 8 + group;
                b[ni][0] = Bu[(ks + tl) * B_ST + nb];
                b[ni][1] = Bu[(ks + tl + 4) * B_ST + nb];
            }
#pragma unroll
            for (int mi = 0; mi < 4; mi++)
#pragma unroll
                for (int ni = 0; ni < 4; ni++)
                    MMA_TF32(acc[mi][ni], a[mi], b[ni]);
        }

        if (c + 1 < NCH)                // store next chunk into other buffer
            store_stage((c + 1) & 1, aR0, aR1, bR0, bR1);
        __syncthreads();
    }

    // ---- epilogue: per-column bias, optional relu, fragment store ----
    float2 bn[4];
#pragma unroll
    for (int ni = 0; ni < 4; ni++) {
        int col = n0 + wn + ni * 8 + tl * 2;
        bn[ni] = *(const float2*)&b1e[col];
        if (MODE == 2) {
            float2 c2 = *(const float2*)&b2e[col];
            bn[ni].x += c2.x; bn[ni].y += c2.y;
        }
    }

    float* Cb;
    if (MODE == 1)      Cb = g_H   + (size_t)e * CAP * NDIM;
    else if (MODE == 2) Cb = g_MID + (size_t)e * CAP * NDIM;
    else                Cb = g_PO  + (size_t)e * CAP * NDIM;

#pragma unroll
    for (int mi = 0; mi < 4; mi++) {
        int r0 = m0 + wm + mi * 16 + group;
        int r1 = r0 + 8;
        float* crow0 = Cb + (size_t)r0 * NDIM;
        float* crow1 = Cb + (size_t)r1 * NDIM;
#pragma unroll
        for (int ni = 0; ni < 4; ni++) {
            int col = n0 + wn + ni * 8 + tl * 2;
            float2 v0, v1;
            v0.x = acc[mi][ni][0] + bn[ni].x;
            v0.y = acc[mi][ni][1] + bn[ni].y;
            v1.x = acc[mi][ni][2] + bn[ni].x;
            v1.y = acc[mi][ni][3] + bn[ni].y;
            if (RELU) {
                v0.x = fmaxf(v0.x, 0.f); v0.y = fmaxf(v0.y, 0.f);
                v1.x = fmaxf(v1.x, 0.f); v1.y = fmaxf(v1.y, 0.f);
            }
            if (r0 < mcount) *(float2*)&crow0[col] = v0;
            if (r1 < mcount) *(float2*)&crow1[col] = v1;
        }
    }
}

// =================================================================
// Combine: out[t] = w0 * PO[p0] + w1 * PO[p1]  (deterministic)
// =================================================================
__global__ void combine_kernel(float* __restrict__ out) {
    const int t = blockIdx.x;
    const int p0 = g_pairpos[2 * t], p1 = g_pairpos[2 * t + 1];
    const float w0 = g_pairw[2 * t], w1 = g_pairw[2 * t + 1];
    const float4* r0 = (const float4*)(g_PO + (size_t)p0 * DOUT);
    const float4* r1 = (const float4*)(g_PO + (size_t)p1 * DOUT);
    float4* o = (float4*)(out + (size_t)t * DOUT);
    for (int c = threadIdx.x; c < DOUT / 4; c += blockDim.x) {
        float4 a = r0[c], b = r1[c], v;
        v.x = w0 * a.x + w1 * b.x;
        v.y = w0 * a.y + w1 * b.y;
        v.z = w0 * a.z + w1 * b.z;
        v.w = w0 * a.w + w1 * b.w;
        o[c] = v;
    }
}

// =================================================================
// Launch
// =================================================================
extern "C" void kernel_launch(void* const* d_in, const int* in_sizes, int n_in,
                              void* d_out, int out_size) {
    (void)in_sizes; (void)n_in; (void)out_size;
    const float* x   = (const float*)d_in[0];
    const float* w1  = (const float*)d_in[1];
    const float* b1  = (const float*)d_in[2];
    const float* w2  = (const float*)d_in[3];
    const float* b2  = (const float*)d_in[4];
    const float* w3  = (const float*)d_in[5];
    const float* b3  = (const float*)d_in[6];
    const float* wp  = (const float*)d_in[7];
    const float* bp  = (const float*)d_in[8];
    const float* gw1 = (const float*)d_in[9];
    const float* gb1 = (const float*)d_in[10];
    const float* gw2 = (const float*)d_in[11];
    const float* gb2 = (const float*)d_in[12];
    float* out = (float*)d_out;

    reset_counts_kernel<<<1, 32>>>();

    // Gating GEMM (exact fp32): g1 = relu(x @ gw1 + gb1)
    {
        dim3 grid(GHID / 128, B_TOK / 128, 1);
        gating_gemm_kernel<<<grid, 256>>>(x, gw1, gb1);
    }

    // Top-2 + softmax + scatter
    gating_topk_scatter_kernel<<<B_TOK, 128>>>(gw2, gb2);

    // GEMM1 (tf32): H = relu(x[tok] @ w1[e] + b1[e])
    {
        dim3 grid(HID / 128, CAP / 128, NEXP);
        moe_mma_kernel<1, DIN, HID, true><<<grid, 256>>>(
            x, w1, nullptr, b1, nullptr);
    }

    // GEMM2 (tf32, fused wp): MID = relu([H | x] @ [w2; wp] + b2 + bp)
    {
        dim3 grid(HID / 128, CAP / 128, NEXP);
        moe_mma_kernel<2, HID + DIN, HID, true><<<grid, 256>>>(
            x, w2, wp, b2, bp);
    }

    // GEMM3 (tf32): PO = MID @ w3[e] + b3[e]
    {
        dim3 grid(DOUT / 128, CAP / 128, NEXP);
        moe_mma_kernel<3, HID, DOUT, false><<<grid, 256>>>(
            x, w3, nullptr, b3, nullptr);
    }

    // Weighted combine into output
    combine_kernel<<<B_TOK, 256>>>(out);
}

// round 8
// speedup vs baseline: 3.0552x; 1.5322x over previous
#include <cuda_runtime.h>
#include <math.h>

// Problem constants (match reference)
#define B_TOK 8192
#define DIN   1024
#define HID   2048
#define DOUT  1024
#define NEXP  8
#define GHID  1024
#define CAP   8192   // worst-case tokens per expert

// -------- device scratch (static globals; allocation-free) --------
__device__ float g_g1[(size_t)B_TOK * GHID];          //  32 MB  gating hidden
__device__ float g_H  [(size_t)NEXP * CAP * HID];     // 512 MB  relu(x@w1+b1)
__device__ float g_MID[(size_t)NEXP * CAP * HID];     // 512 MB  relu(h@w2 + x@wp + b)
__device__ float g_PO [(size_t)NEXP * CAP * DOUT];    // 256 MB  expert outputs
__device__ int   g_count[NEXP];
__device__ int   g_tok[NEXP * CAP];
__device__ int   g_pairpos[B_TOK * 2];
__device__ float g_pairw [B_TOK * 2];

__device__ __forceinline__ unsigned f2tf(float f) {
    unsigned u;
    asm("cvt.rna.tf32.f32 %0, %1;" : "=r"(u) : "f"(f));
    return u;
}

// =================================================================
// Reset per-expert counters (must run every graph replay)
// =================================================================
__global__ void reset_counts_kernel() {
    if (threadIdx.x < NEXP) g_count[threadIdx.x] = 0;
}

// =================================================================
// Gating epilogue: logits = relu_g1 @ gw2 + gb2 ; top-2 ; softmax ;
// scatter. FP32 throughout — selection must match reference exactly.
// =================================================================
__global__ void gating_topk_scatter_kernel(const float* __restrict__ gw2,
                                           const float* __restrict__ gb2) {
    const int t   = blockIdx.x;
    const int tid = threadIdx.x;

    float acc[NEXP];
#pragma unroll
    for (int e = 0; e < NEXP; e++) acc[e] = 0.f;

    const float* row = g_g1 + (size_t)t * GHID;
    for (int k = tid; k < GHID; k += 128) {
        float v = row[k];
        const float* w = gw2 + (size_t)k * NEXP;
#pragma unroll
        for (int e = 0; e < NEXP; e++) acc[e] += v * w[e];
    }

    __shared__ float sm[128 * NEXP];
#pragma unroll
    for (int e = 0; e < NEXP; e++) sm[tid * NEXP + e] = acc[e];
    __syncthreads();
    for (int s = 64; s > 0; s >>= 1) {
        if (tid < s) {
#pragma unroll
            for (int e = 0; e < NEXP; e++)
                sm[tid * NEXP + e] += sm[(tid + s) * NEXP + e];
        }
        __syncthreads();
    }

    if (tid == 0) {
        float l[NEXP];
#pragma unroll
        for (int e = 0; e < NEXP; e++) l[e] = sm[e] + gb2[e];

        int i0 = 0;
#pragma unroll
        for (int e = 1; e < NEXP; e++) if (l[e] > l[i0]) i0 = e;
        int i1 = -1;
#pragma unroll
        for (int e = 0; e < NEXP; e++) {
            if (e == i0) continue;
            if (i1 < 0 || l[e] > l[i1]) i1 = e;
        }
        float r  = expf(l[i1] - l[i0]);
        float w0 = 1.f / (1.f + r);
        float w1 = r / (1.f + r);

        int p0 = atomicAdd(&g_count[i0], 1);
        int s0 = i0 * CAP + p0;
        g_tok[s0] = t; g_pairpos[2 * t] = s0; g_pairw[2 * t] = w0;

        int p1 = atomicAdd(&g_count[i1], 1);
        int s1 = i1 * CAP + p1;
        g_tok[s1] = t; g_pairpos[2 * t + 1] = s1; g_pairw[2 * t + 1] = w1;
    }
}

// =================================================================
// FP32 gating GEMM (exact): g1 = relu(x @ gw1 + gb1)
// =================================================================
__global__ void __launch_bounds__(256) gating_gemm_kernel(
    const float* __restrict__ x,
    const float* __restrict__ W,
    const float* __restrict__ bias) {

    __shared__ float As[16][128];
    __shared__ float Bs[16][128];

    const int m0 = blockIdx.y * 128;
    const int n0 = blockIdx.x * 128;
    const int tid = threadIdx.x;

    const int ra0 = tid >> 2;
    const int ra1 = 64 + ra0;
    const int kv4 = (tid & 3) * 4;
    const int kb0 = tid >> 5;
    const int kb1 = 8 + kb0;
    const int nv4 = (tid & 31) * 4;

    const float* arow0 = x + (size_t)(m0 + ra0) * DIN;
    const float* arow1 = x + (size_t)(m0 + ra1) * DIN;

    float acc[8][8];
#pragma unroll
    for (int i = 0; i < 8; i++)
#pragma unroll
        for (int j = 0; j < 8; j++) acc[i][j] = 0.f;

    const int ty = tid >> 4;
    const int tx = tid & 15;

    float4 aR0 = *(const float4*)(arow0 + kv4);
    float4 aR1 = *(const float4*)(arow1 + kv4);
    float4 bR0 = *(const float4*)(W + (size_t)kb0 * GHID + n0 + nv4);
    float4 bR1 = *(const float4*)(W + (size_t)kb1 * GHID + n0 + nv4);

    for (int kt = 0; kt < DIN; kt += 16) {
        As[kv4 + 0][ra0] = aR0.x; As[kv4 + 1][ra0] = aR0.y;
        As[kv4 + 2][ra0] = aR0.z; As[kv4 + 3][ra0] = aR0.w;
        As[kv4 + 0][ra1] = aR1.x; As[kv4 + 1][ra1] = aR1.y;
        As[kv4 + 2][ra1] = aR1.z; As[kv4 + 3][ra1] = aR1.w;
        *(float4*)&Bs[kb0][nv4] = bR0;
        *(float4*)&Bs[kb1][nv4] = bR1;
        __syncthreads();

        if (kt + 16 < DIN) {
            aR0 = *(const float4*)(arow0 + kt + 16 + kv4);
            aR1 = *(const float4*)(arow1 + kt + 16 + kv4);
            bR0 = *(const float4*)(W + (size_t)(kt + 16 + kb0) * GHID + n0 + nv4);
            bR1 = *(const float4*)(W + (size_t)(kt + 16 + kb1) * GHID + n0 + nv4);
        }

#pragma unroll
        for (int kk = 0; kk < 16; kk++) {
            float a[8], b[8];
            *(float4*)&a[0] = *(const float4*)&As[kk][4 * ty];
            *(float4*)&a[4] = *(const float4*)&As[kk][64 + 4 * ty];
            *(float4*)&b[0] = *(const float4*)&Bs[kk][4 * tx];
            *(float4*)&b[4] = *(const float4*)&Bs[kk][64 + 4 * tx];
#pragma unroll
            for (int i = 0; i < 8; i++)
#pragma unroll
                for (int j = 0; j < 8; j++) acc[i][j] += a[i] * b[j];
        }
        __syncthreads();
    }

    float bn[8];
    {
        float4 b0 = *(const float4*)&bias[n0 + 4 * tx];
        float4 b1 = *(const float4*)&bias[n0 + 64 + 4 * tx];
        bn[0] = b0.x; bn[1] = b0.y; bn[2] = b0.z; bn[3] = b0.w;
        bn[4] = b1.x; bn[5] = b1.y; bn[6] = b1.z; bn[7] = b1.w;
    }

#pragma unroll
    for (int i = 0; i < 8; i++) {
        int m = m0 + ((i < 4) ? (4 * ty + i) : (64 + 4 * ty + (i - 4)));
        float* crow = g_g1 + (size_t)m * GHID;
        float4 v0, v1;
        v0.x = fmaxf(acc[i][0] + bn[0], 0.f); v0.y = fmaxf(acc[i][1] + bn[1], 0.f);
        v0.z = fmaxf(acc[i][2] + bn[2], 0.f); v0.w = fmaxf(acc[i][3] + bn[3], 0.f);
        v1.x = fmaxf(acc[i][4] + bn[4], 0.f); v1.y = fmaxf(acc[i][5] + bn[5], 0.f);
        v1.z = fmaxf(acc[i][6] + bn[6], 0.f); v1.w = fmaxf(acc[i][7] + bn[7], 0.f);
        *(float4*)&crow[n0 + 4 * tx]      = v0;
        *(float4*)&crow[n0 + 64 + 4 * tx] = v1;
    }
}

// =================================================================
// TF32 tensor-core grouped GEMM, double-buffered smem, A fragments
// via ldmatrix.x4.b16 (16x8 tf32 tile == 16x16 b16 tile; LDSM row
// pointers at stride 20 floats hit 8 disjoint 4-bank groups ->
// conflict-free; rows 16B-aligned). 2 CTAs/SM for latency hiding.
// Numerics identical to the passing R5/R7 builds (cvt.rna on the
// smem-store path).
// MODE 1: H   = relu(x[tok] @ w1[e] + b1[e])           K=DIN
// MODE 2: MID = relu([H | x[tok]] @ [w2;wp] + b2+bp)   K=HID+DIN
// MODE 3: PO  = MID @ w3[e] + b3[e]                    K=HID
// =================================================================
#define MMA_TF32(d, a, b)                                                    \
    asm volatile(                                                            \
        "mma.sync.aligned.m16n8k8.row.col.f32.tf32.tf32.f32 "                \
        "{%0,%1,%2,%3}, {%4,%5,%6,%7}, {%8,%9}, {%0,%1,%2,%3};\n"            \
        : "+f"((d)[0]), "+f"((d)[1]), "+f"((d)[2]), "+f"((d)[3])             \
        : "r"((a)[0]), "r"((a)[1]), "r"((a)[2]), "r"((a)[3]),                \
          "r"((b)[0]), "r"((b)[1]))

#define LDSM_X4(r, addr)                                                     \
    asm volatile(                                                            \
        "ldmatrix.sync.aligned.m8n8.x4.shared.b16 {%0,%1,%2,%3}, [%4];\n"    \
        : "=r"((r)[0]), "=r"((r)[1]), "=r"((r)[2]), "=r"((r)[3])             \
        : "r"(addr))

#define A_ST 20    // A smem stride (floats)
#define B_ST 136   // B smem stride (floats)

template <int MODE, int KDIM, int NDIM, bool RELU>
__global__ void __launch_bounds__(256, 2) moe_mma_kernel(
    const float* __restrict__ x,
    const float* __restrict__ Wa,
    const float* __restrict__ Wb,
    const float* __restrict__ ba,
    const float* __restrict__ bb) {

    __shared__ unsigned As[2][128 * A_ST];   // [stage][m][k]
    __shared__ unsigned Bs[2][16 * B_ST];    // [stage][k][n]

    const int e = (int)blockIdx.z;
    const int mcount = g_count[e];
    const int m0 = blockIdx.y * 128;
    if (m0 >= mcount) return;
    const int n0 = blockIdx.x * 128;
    const int tid  = threadIdx.x;
    const int lane = tid & 31;
    const int warp = tid >> 5;
    const int wm = (warp & 1) * 64;
    const int wn = (warp >> 1) * 32;
    const int group = lane >> 2;
    const int tl    = lane & 3;

    // global->smem load mapping
    const int ra0 = tid >> 2;          // A rows ra0 and ra0+64
    const int kv4 = (tid & 3) * 4;
    const int kb0 = tid >> 5;          // B k-rows kb0 and kb0+8
    const int nv4 = (tid & 31) * 4;

    // expert weight/bias pointers
    const float* W1e = Wa;
    const float* W2e = Wb;
    const float* b1e = ba;
    const float* b2e = bb;
    if (MODE == 1)      { W1e += (size_t)e * DIN * HID;  b1e += (size_t)e * HID; }
    else if (MODE == 2) { W1e += (size_t)e * HID * HID;  W2e += (size_t)e * DIN * HID;
                          b1e += (size_t)e * HID;        b2e += (size_t)e * HID; }
    else                { W1e += (size_t)e * HID * DOUT; b1e += (size_t)e * DOUT; }

    // A row base pointers (rows >= mcount read valid stale slots; never stored)
    const float* arow0; const float* arow1;
    const float* xrow0 = x; const float* xrow1 = x;
    if (MODE == 1) {
        arow0 = x + (size_t)g_tok[e * CAP + m0 + ra0] * DIN;
        arow1 = x + (size_t)g_tok[e * CAP + m0 + 64 + ra0] * DIN;
    } else if (MODE == 2) {
        xrow0 = x + (size_t)g_tok[e * CAP + m0 + ra0] * DIN;
        xrow1 = x + (size_t)g_tok[e * CAP + m0 + 64 + ra0] * DIN;
        arow0 = g_H + (size_t)(e * CAP + m0 + ra0) * HID;
        arow1 = g_H + (size_t)(e * CAP + m0 + 64 + ra0) * HID;
    } else {
        arow0 = g_MID + (size_t)(e * CAP + m0 + ra0) * HID;
        arow1 = g_MID + (size_t)(e * CAP + m0 + 64 + ra0) * HID;
    }

    auto loadA = [&](int kt, float4& A0, float4& A1) {
        if (MODE == 2 && kt >= HID) {
            int k = kt - HID + kv4;
            A0 = *(const float4*)(xrow0 + k);
            A1 = *(const float4*)(xrow1 + k);
        } else {
            int k = kt + kv4;
            A0 = *(const float4*)(arow0 + k);
            A1 = *(const float4*)(arow1 + k);
        }
    };
    auto loadB = [&](int kt, float4& B0, float4& B1) {
        const float* wsrc = W1e;
        int kloc = kt;
        if (MODE == 2 && kt >= HID) { wsrc = W2e; kloc = kt - HID; }
        B0 = *(const float4*)(wsrc + (size_t)(kloc + kb0) * NDIM + n0 + nv4);
        B1 = *(const float4*)(wsrc + (size_t)(kloc + kb0 + 8) * NDIM + n0 + nv4);
    };

    auto store_stage = [&](int s, const float4& A0, const float4& A1,
                                  const float4& B0, const float4& B1) {
        uint4 u;
        u = make_uint4(f2tf(A0.x), f2tf(A0.y), f2tf(A0.z), f2tf(A0.w));
        *(uint4*)&As[s][ra0 * A_ST + kv4] = u;
        u = make_uint4(f2tf(A1.x), f2tf(A1.y), f2tf(A1.z), f2tf(A1.w));
        *(uint4*)&As[s][(64 + ra0) * A_ST + kv4] = u;
        u = make_uint4(f2tf(B0.x), f2tf(B0.y), f2tf(B0.z), f2tf(B0.w));
        *(uint4*)&Bs[s][kb0 * B_ST + nv4] = u;
        u = make_uint4(f2tf(B1.x), f2tf(B1.y), f2tf(B1.z), f2tf(B1.w));
        *(uint4*)&Bs[s][(8 + kb0) * B_ST + nv4] = u;
    };

    float acc[4][4][4];
#pragma unroll
    for (int mi = 0; mi < 4; mi++)
#pragma unroll
        for (int ni = 0; ni < 4; ni++)
#pragma unroll
            for (int r = 0; r < 4; r++) acc[mi][ni][r] = 0.f;

    float4 aR0, aR1, bR0, bR1;
    loadA(0, aR0, aR1);
    loadB(0, bR0, bR1);
    store_stage(0, aR0, aR1, bR0, bR1);
    __syncthreads();

    // per-thread LDSM base address (bytes, shared space):
    //   row = wm + (lane & 15), k-offset = (lane >> 4) * 4
    const unsigned aLdsmBase = (unsigned)__cvta_generic_to_shared(&As[0][0])
        + (unsigned)(((wm + (lane & 15)) * A_ST + ((lane >> 4) << 2)) * 4);

    const int NCH = KDIM / 16;
#pragma unroll 1
    for (int c = 0; c < NCH; c++) {
        if (c + 1 < NCH) {              // issue next chunk's global loads
            loadA((c + 1) * 16, aR0, aR1);
            loadB((c + 1) * 16, bR0, bR1);
        }

        const unsigned aStage = aLdsmBase + (unsigned)((c & 1) * 128 * A_ST * 4);
        const unsigned* Bu = Bs[c & 1];
#pragma unroll
        for (int ks = 0; ks < 16; ks += 8) {
            unsigned a[4][4], b[4][2];
#pragma unroll
            for (int mi = 0; mi < 4; mi++)
                LDSM_X4(a[mi], aStage + (unsigned)((mi * 16 * A_ST + ks) * 4));
#pragma unroll
            for (int ni = 0; ni < 4; ni++) {
                int nb = wn + ni * 8 + group;
                b[ni][0] = Bu[(ks + tl) * B_ST + nb];
                b[ni][1] = Bu[(ks + tl + 4) * B_ST + nb];
            }
#pragma unroll
            for (int mi = 0; mi < 4; mi++)
#pragma unroll
                for (int ni = 0; ni < 4; ni++)
                    MMA_TF32(acc[mi][ni], a[mi], b[ni]);
        }

        if (c + 1 < NCH)                // store next chunk into other buffer
            store_stage((c + 1) & 1, aR0, aR1, bR0, bR1);
        __syncthreads();
    }

    // ---- epilogue: per-column bias, optional relu, fragment store ----
    float2 bn[4];
#pragma unroll
    for (int ni = 0; ni < 4; ni++) {
        int col = n0 + wn + ni * 8 + tl * 2;
        bn[ni] = *(const float2*)&b1e[col];
        if (MODE == 2) {
            float2 c2 = *(const float2*)&b2e[col];
            bn[ni].x += c2.x; bn[ni].y += c2.y;
        }
    }

    float* Cb;
    if (MODE == 1)      Cb = g_H   + (size_t)e * CAP * NDIM;
    else if (MODE == 2) Cb = g_MID + (size_t)e * CAP * NDIM;
    else                Cb = g_PO  + (size_t)e * CAP * NDIM;

#pragma unroll
    for (int mi = 0; mi < 4; mi++) {
        int r0 = m0 + wm + mi * 16 + group;
        int r1 = r0 + 8;
        float* crow0 = Cb + (size_t)r0 * NDIM;
        float* crow1 = Cb + (size_t)r1 * NDIM;
#pragma unroll
        for (int ni = 0; ni < 4; ni++) {
            int col = n0 + wn + ni * 8 + tl * 2;
            float2 v0, v1;
            v0.x = acc[mi][ni][0] + bn[ni].x;
            v0.y = acc[mi][ni][1] + bn[ni].y;
            v1.x = acc[mi][ni][2] + bn[ni].x;
            v1.y = acc[mi][ni][3] + bn[ni].y;
            if (RELU) {
                v0.x = fmaxf(v0.x, 0.f); v0.y = fmaxf(v0.y, 0.f);
                v1.x = fmaxf(v1.x, 0.f); v1.y = fmaxf(v1.y, 0.f);
            }
            if (r0 < mcount) *(float2*)&crow0[col] = v0;
            if (r1 < mcount) *(float2*)&crow1[col] = v1;
        }
    }
}

// =================================================================
// Combine: out[t] = w0 * PO[p0] + w1 * PO[p1]  (deterministic)
// =================================================================
__global__ void combine_kernel(float* __restrict__ out) {
    const int t = blockIdx.x;
    const int p0 = g_pairpos[2 * t], p1 = g_pairpos[2 * t + 1];
    const float w0 = g_pairw[2 * t], w1 = g_pairw[2 * t + 1];
    const float4* r0 = (const float4*)(g_PO + (size_t)p0 * DOUT);
    const float4* r1 = (const float4*)(g_PO + (size_t)p1 * DOUT);
    float4* o = (float4*)(out + (size_t)t * DOUT);
    for (int c = threadIdx.x; c < DOUT / 4; c += blockDim.x) {
        float4 a = r0[c], b = r1[c], v;
        v.x = w0 * a.x + w1 * b.x;
        v.y = w0 * a.y + w1 * b.y;
        v.z = w0 * a.z + w1 * b.z;
        v.w = w0 * a.w + w1 * b.w;
        o[c] = v;
    }
}

// =================================================================
// Launch
// =================================================================
extern "C" void kernel_launch(void* const* d_in, const int* in_sizes, int n_in,
                              void* d_out, int out_size) {
    (void)in_sizes; (void)n_in; (void)out_size;
    const float* x   = (const float*)d_in[0];
    const float* w1  = (const float*)d_in[1];
    const float* b1  = (const float*)d_in[2];
    const float* w2  = (const float*)d_in[3];
    const float* b2  = (const float*)d_in[4];
    const float* w3  = (const float*)d_in[5];
    const float* b3  = (const float*)d_in[6];
    const float* wp  = (const float*)d_in[7];
    const float* bp  = (const float*)d_in[8];
    const float* gw1 = (const float*)d_in[9];
    const float* gb1 = (const float*)d_in[10];
    const float* gw2 = (const float*)d_in[11];
    const float* gb2 = (const float*)d_in[12];
    float* out = (float*)d_out;

    reset_counts_kernel<<<1, 32>>>();

    // Gating GEMM (exact fp32): g1 = relu(x @ gw1 + gb1)
    {
        dim3 grid(GHID / 128, B_TOK / 128, 1);
        gating_gemm_kernel<<<grid, 256>>>(x, gw1, gb1);
    }

    // Top-2 + softmax + scatter
    gating_topk_scatter_kernel<<<B_TOK, 128>>>(gw2, gb2);

    // GEMM1 (tf32): H = relu(x[tok] @ w1[e] + b1[e])
    {
        dim3 grid(HID / 128, CAP / 128, NEXP);
        moe_mma_kernel<1, DIN, HID, true><<<grid, 256>>>(
            x, w1, nullptr, b1, nullptr);
    }

    // GEMM2 (tf32, fused wp): MID = relu([H | x] @ [w2; wp] + b2 + bp)
    {
        dim3 grid(HID / 128, CAP / 128, NEXP);
        moe_mma_kernel<2, HID + DIN, HID, true><<<grid, 256>>>(
            x, w2, wp, b2, bp);
    }

    // GEMM3 (tf32): PO = MID @ w3[e] + b3[e]
    {
        dim3 grid(DOUT / 128, CAP / 128, NEXP);
        moe_mma_kernel<3, HID, DOUT, false><<<grid, 256>>>(
            x, w3, nullptr, b3, nullptr);
    }

    // Weighted combine into output
    combine_kernel<<<B_TOK, 256>>>(out);
}

// round 10
// speedup vs baseline: 3.0621x; 1.0022x over previous
#include <cuda_runtime.h>
#include <math.h>

// Problem constants (match reference)
#define B_TOK 8192
#define DIN   1024
#define HID   2048
#define DOUT  1024
#define NEXP  8
#define GHID  1024
#define CAP   8192   // worst-case tokens per expert

// -------- device scratch (static globals; allocation-free) --------
__device__ float g_g1[(size_t)B_TOK * GHID];          //  32 MB  gating hidden
__device__ float g_H  [(size_t)NEXP * CAP * HID];     // 512 MB  relu(x@w1+b1)
__device__ float g_MID[(size_t)NEXP * CAP * HID];     // 512 MB  relu(h@w2 + x@wp + b)
__device__ float g_PO [(size_t)NEXP * CAP * DOUT];    // 256 MB  expert outputs
__device__ int   g_count[NEXP];
__device__ int   g_tok[NEXP * CAP];
__device__ int   g_pairpos[B_TOK * 2];
__device__ float g_pairw [B_TOK * 2];

__device__ __forceinline__ unsigned f2tf(float f) {
    unsigned u;
    asm("cvt.rna.tf32.f32 %0, %1;" : "=r"(u) : "f"(f));
    return u;
}

// =================================================================
// Reset per-expert counters (must run every graph replay)
// =================================================================
__global__ void reset_counts_kernel() {
    if (threadIdx.x < NEXP) g_count[threadIdx.x] = 0;
}

// =================================================================
// Gating epilogue: logits = relu_g1 @ gw2 + gb2 ; top-2 ; softmax ;
// scatter. FP32 throughout — selection must match reference exactly.
// =================================================================
__global__ void gating_topk_scatter_kernel(const float* __restrict__ gw2,
                                           const float* __restrict__ gb2) {
    const int t   = blockIdx.x;
    const int tid = threadIdx.x;

    float acc[NEXP];
#pragma unroll
    for (int e = 0; e < NEXP; e++) acc[e] = 0.f;

    const float* row = g_g1 + (size_t)t * GHID;
    for (int k = tid; k < GHID; k += 128) {
        float v = row[k];
        const float* w = gw2 + (size_t)k * NEXP;
#pragma unroll
        for (int e = 0; e < NEXP; e++) acc[e] += v * w[e];
    }

    __shared__ float sm[128 * NEXP];
#pragma unroll
    for (int e = 0; e < NEXP; e++) sm[tid * NEXP + e] = acc[e];
    __syncthreads();
    for (int s = 64; s > 0; s >>= 1) {
        if (tid < s) {
#pragma unroll
            for (int e = 0; e < NEXP; e++)
                sm[tid * NEXP + e] += sm[(tid + s) * NEXP + e];
        }
        __syncthreads();
    }

    if (tid == 0) {
        float l[NEXP];
#pragma unroll
        for (int e = 0; e < NEXP; e++) l[e] = sm[e] + gb2[e];

        int i0 = 0;
#pragma unroll
        for (int e = 1; e < NEXP; e++) if (l[e] > l[i0]) i0 = e;
        int i1 = -1;
#pragma unroll
        for (int e = 0; e < NEXP; e++) {
            if (e == i0) continue;
            if (i1 < 0 || l[e] > l[i1]) i1 = e;
        }
        float r  = expf(l[i1] - l[i0]);
        float w0 = 1.f / (1.f + r);
        float w1 = r / (1.f + r);

        int p0 = atomicAdd(&g_count[i0], 1);
        int s0 = i0 * CAP + p0;
        g_tok[s0] = t; g_pairpos[2 * t] = s0; g_pairw[2 * t] = w0;

        int p1 = atomicAdd(&g_count[i1], 1);
        int s1 = i1 * CAP + p1;
        g_tok[s1] = t; g_pairpos[2 * t + 1] = s1; g_pairw[2 * t + 1] = w1;
    }
}

// =================================================================
// FP32 gating GEMM (exact): g1 = relu(x @ gw1 + gb1)
// =================================================================
__global__ void __launch_bounds__(256) gating_gemm_kernel(
    const float* __restrict__ x,
    const float* __restrict__ W,
    const float* __restrict__ bias) {

    __shared__ float As[16][128];
    __shared__ float Bs[16][128];

    const int m0 = blockIdx.y * 128;
    const int n0 = blockIdx.x * 128;
    const int tid = threadIdx.x;

    const int ra0 = tid >> 2;
    const int ra1 = 64 + ra0;
    const int kv4 = (tid & 3) * 4;
    const int kb0 = tid >> 5;
    const int kb1 = 8 + kb0;
    const int nv4 = (tid & 31) * 4;

    const float* arow0 = x + (size_t)(m0 + ra0) * DIN;
    const float* arow1 = x + (size_t)(m0 + ra1) * DIN;

    float acc[8][8];
#pragma unroll
    for (int i = 0; i < 8; i++)
#pragma unroll
        for (int j = 0; j < 8; j++) acc[i][j] = 0.f;

    const int ty = tid >> 4;
    const int tx = tid & 15;

    float4 aR0 = *(const float4*)(arow0 + kv4);
    float4 aR1 = *(const float4*)(arow1 + kv4);
    float4 bR0 = *(const float4*)(W + (size_t)kb0 * GHID + n0 + nv4);
    float4 bR1 = *(const float4*)(W + (size_t)kb1 * GHID + n0 + nv4);

    for (int kt = 0; kt < DIN; kt += 16) {
        As[kv4 + 0][ra0] = aR0.x; As[kv4 + 1][ra0] = aR0.y;
        As[kv4 + 2][ra0] = aR0.z; As[kv4 + 3][ra0] = aR0.w;
        As[kv4 + 0][ra1] = aR1.x; As[kv4 + 1][ra1] = aR1.y;
        As[kv4 + 2][ra1] = aR1.z; As[kv4 + 3][ra1] = aR1.w;
        *(float4*)&Bs[kb0][nv4] = bR0;
        *(float4*)&Bs[kb1][nv4] = bR1;
        __syncthreads();

        if (kt + 16 < DIN) {
            aR0 = *(const float4*)(arow0 + kt + 16 + kv4);
            aR1 = *(const float4*)(arow1 + kt + 16 + kv4);
            bR0 = *(const float4*)(W + (size_t)(kt + 16 + kb0) * GHID + n0 + nv4);
            bR1 = *(const float4*)(W + (size_t)(kt + 16 + kb1) * GHID + n0 + nv4);
        }

#pragma unroll
        for (int kk = 0; kk < 16; kk++) {
            float a[8], b[8];
            *(float4*)&a[0] = *(const float4*)&As[kk][4 * ty];
            *(float4*)&a[4] = *(const float4*)&As[kk][64 + 4 * ty];
            *(float4*)&b[0] = *(const float4*)&Bs[kk][4 * tx];
            *(float4*)&b[4] = *(const float4*)&Bs[kk][64 + 4 * tx];
#pragma unroll
            for (int i = 0; i < 8; i++)
#pragma unroll
                for (int j = 0; j < 8; j++) acc[i][j] += a[i] * b[j];
        }
        __syncthreads();
    }

    float bn[8];
    {
        float4 b0 = *(const float4*)&bias[n0 + 4 * tx];
        float4 b1 = *(const float4*)&bias[n0 + 64 + 4 * tx];
        bn[0] = b0.x; bn[1] = b0.y; bn[2] = b0.z; bn[3] = b0.w;
        bn[4] = b1.x; bn[5] = b1.y; bn[6] = b1.z; bn[7] = b1.w;
    }

#pragma unroll
    for (int i = 0; i < 8; i++) {
        int m = m0 + ((i < 4) ? (4 * ty + i) : (64 + 4 * ty + (i - 4)));
        float* crow = g_g1 + (size_t)m * GHID;
        float4 v0, v1;
        v0.x = fmaxf(acc[i][0] + bn[0], 0.f); v0.y = fmaxf(acc[i][1] + bn[1], 0.f);
        v0.z = fmaxf(acc[i][2] + bn[2], 0.f); v0.w = fmaxf(acc[i][3] + bn[3], 0.f);
        v1.x = fmaxf(acc[i][4] + bn[4], 0.f); v1.y = fmaxf(acc[i][5] + bn[5], 0.f);
        v1.z = fmaxf(acc[i][6] + bn[6], 0.f); v1.w = fmaxf(acc[i][7] + bn[7], 0.f);
        *(float4*)&crow[n0 + 4 * tx]      = v0;
        *(float4*)&crow[n0 + 64 + 4 * tx] = v1;
    }
}

// =================================================================
// TF32 tensor-core grouped GEMM, double-buffered smem, A fragments
// via ldmatrix.x4.b16 (16x8 tf32 tile == 16x16 b16 tile; LDSM row
// pointers at stride 20 floats hit 8 disjoint 4-bank groups ->
// conflict-free; rows 16B-aligned). 2 CTAs/SM for latency hiding.
// Numerics identical to the passing R5/R7 builds (cvt.rna on the
// smem-store path).
// MODE 1: H   = relu(x[tok] @ w1[e] + b1[e])           K=DIN
// MODE 2: MID = relu([H | x[tok]] @ [w2;wp] + b2+bp)   K=HID+DIN
// MODE 3: PO  = MID @ w3[e] + b3[e]                    K=HID
// =================================================================
#define MMA_TF32(d, a, b)                                                    \
    asm volatile(                                                            \
        "mma.sync.aligned.m16n8k8.row.col.f32.tf32.tf32.f32 "                \
        "{%0,%1,%2,%3}, {%4,%5,%6,%7}, {%8,%9}, {%0,%1,%2,%3};\n"            \
        : "+f"((d)[0]), "+f"((d)[1]), "+f"((d)[2]), "+f"((d)[3])             \
        : "r"((a)[0]), "r"((a)[1]), "r"((a)[2]), "r"((a)[3]),                \
          "r"((b)[0]), "r"((b)[1]))

#define LDSM_X4(r, addr)                                                     \
    asm volatile(                                                            \
        "ldmatrix.sync.aligned.m8n8.x4.shared.b16 {%0,%1,%2,%3}, [%4];\n"    \
        : "=r"((r)[0]), "=r"((r)[1]), "=r"((r)[2]), "=r"((r)[3])             \
        : "r"(addr))

#define A_ST 20    // A smem stride (floats)
#define B_ST 136   // B smem stride (floats)

template <int MODE, int KDIM, int NDIM, bool RELU>
__global__ void __launch_bounds__(256, 2) moe_mma_kernel(
    const float* __restrict__ x,
    const float* __restrict__ Wa,
    const float* __restrict__ Wb,
    const float* __restrict__ ba,
    const float* __restrict__ bb) {

    __shared__ unsigned As[2][128 * A_ST];   // [stage][m][k]
    __shared__ unsigned Bs[2][16 * B_ST];    // [stage][k][n]

    const int e = (int)blockIdx.z;
    const int mcount = g_count[e];
    const int m0 = blockIdx.y * 128;
    if (m0 >= mcount) return;
    const int n0 = blockIdx.x * 128;
    const int tid  = threadIdx.x;
    const int lane = tid & 31;
    const int warp = tid >> 5;
    const int wm = (warp & 1) * 64;
    const int wn = (warp >> 1) * 32;
    const int group = lane >> 2;
    const int tl    = lane & 3;

    // global->smem load mapping
    const int ra0 = tid >> 2;          // A rows ra0 and ra0+64
    const int kv4 = (tid & 3) * 4;
    const int kb0 = tid >> 5;          // B k-rows kb0 and kb0+8
    const int nv4 = (tid & 31) * 4;

    // expert weight/bias pointers
    const float* W1e = Wa;
    const float* W2e = Wb;
    const float* b1e = ba;
    const float* b2e = bb;
    if (MODE == 1)      { W1e += (size_t)e * DIN * HID;  b1e += (size_t)e * HID; }
    else if (MODE == 2) { W1e += (size_t)e * HID * HID;  W2e += (size_t)e * DIN * HID;
                          b1e += (size_t)e * HID;        b2e += (size_t)e * HID; }
    else                { W1e += (size_t)e * HID * DOUT; b1e += (size_t)e * DOUT; }

    // A row base pointers (rows >= mcount read valid stale slots; never stored)
    const float* arow0; const float* arow1;
    const float* xrow0 = x; const float* xrow1 = x;
    if (MODE == 1) {
        arow0 = x + (size_t)g_tok[e * CAP + m0 + ra0] * DIN;
        arow1 = x + (size_t)g_tok[e * CAP + m0 + 64 + ra0] * DIN;
    } else if (MODE == 2) {
        xrow0 = x + (size_t)g_tok[e * CAP + m0 + ra0] * DIN;
        xrow1 = x + (size_t)g_tok[e * CAP + m0 + 64 + ra0] * DIN;
        arow0 = g_H + (size_t)(e * CAP + m0 + ra0) * HID;
        arow1 = g_H + (size_t)(e * CAP + m0 + 64 + ra0) * HID;
    } else {
        arow0 = g_MID + (size_t)(e * CAP + m0 + ra0) * HID;
        arow1 = g_MID + (size_t)(e * CAP + m0 + 64 + ra0) * HID;
    }

    auto loadA = [&](int kt, float4& A0, float4& A1) {
        if (MODE == 2 && kt >= HID) {
            int k = kt - HID + kv4;
            A0 = *(const float4*)(xrow0 + k);
            A1 = *(const float4*)(xrow1 + k);
        } else {
            int k = kt + kv4;
            A0 = *(const float4*)(arow0 + k);
            A1 = *(const float4*)(arow1 + k);
        }
    };
    auto loadB = [&](int kt, float4& B0, float4& B1) {
        const float* wsrc = W1e;
        int kloc = kt;
        if (MODE == 2 && kt >= HID) { wsrc = W2e; kloc = kt - HID; }
        B0 = *(const float4*)(wsrc + (size_t)(kloc + kb0) * NDIM + n0 + nv4);
        B1 = *(const float4*)(wsrc + (size_t)(kloc + kb0 + 8) * NDIM + n0 + nv4);
    };

    auto store_stage = [&](int s, const float4& A0, const float4& A1,
                                  const float4& B0, const float4& B1) {
        uint4 u;
        u = make_uint4(f2tf(A0.x), f2tf(A0.y), f2tf(A0.z), f2tf(A0.w));
        *(uint4*)&As[s][ra0 * A_ST + kv4] = u;
        u = make_uint4(f2tf(A1.x), f2tf(A1.y), f2tf(A1.z), f2tf(A1.w));
        *(uint4*)&As[s][(64 + ra0) * A_ST + kv4] = u;
        u = make_uint4(f2tf(B0.x), f2tf(B0.y), f2tf(B0.z), f2tf(B0.w));
        *(uint4*)&Bs[s][kb0 * B_ST + nv4] = u;
        u = make_uint4(f2tf(B1.x), f2tf(B1.y), f2tf(B1.z), f2tf(B1.w));
        *(uint4*)&Bs[s][(8 + kb0) * B_ST + nv4] = u;
    };

    float acc[4][4][4];
#pragma unroll
    for (int mi = 0; mi < 4; mi++)
#pragma unroll
        for (int ni = 0; ni < 4; ni++)
#pragma unroll
            for (int r = 0; r < 4; r++) acc[mi][ni][r] = 0.f;

    float4 aR0, aR1, bR0, bR1;
    loadA(0, aR0, aR1);
    loadB(0, bR0, bR1);
    store_stage(0, aR0, aR1, bR0, bR1);
    __syncthreads();

    // per-thread LDSM base address (bytes, shared space):
    //   row = wm + (lane & 15), k-offset = (lane >> 4) * 4
    const unsigned aLdsmBase = (unsigned)__cvta_generic_to_shared(&As[0][0])
        + (unsigned)(((wm + (lane & 15)) * A_ST + ((lane >> 4) << 2)) * 4);

    const int NCH = KDIM / 16;
#pragma unroll 1
    for (int c = 0; c < NCH; c++) {
        if (c + 1 < NCH) {              // issue next chunk's global loads
            loadA((c + 1) * 16, aR0, aR1);
            loadB((c + 1) * 16, bR0, bR1);
        }

        const unsigned aStage = aLdsmBase + (unsigned)((c & 1) * 128 * A_ST * 4);
        const unsigned* Bu = Bs[c & 1];
#pragma unroll
        for (int ks = 0; ks < 16; ks += 8) {
            unsigned a[4][4], b[4][2];
#pragma unroll
            for (int mi = 0; mi < 4; mi++)
                LDSM_X4(a[mi], aStage + (unsigned)((mi * 16 * A_ST + ks) * 4));
#pragma unroll
            for (int ni = 0; ni < 4; ni++) {
                int nb = wn + ni * 8 + group;
                b[ni][0] = Bu[(ks + tl) * B_ST + nb];
                b[ni][1] = Bu[(ks + tl + 4) * B_ST + nb];
            }
#pragma unroll
            for (int mi = 0; mi < 4; mi++)
#pragma unroll
                for (int ni = 0; ni < 4; ni++)
                    MMA_TF32(acc[mi][ni], a[mi], b[ni]);
        }

        if (c + 1 < NCH)                // store next chunk into other buffer
            store_stage((c + 1) & 1, aR0, aR1, bR0, bR1);
        __syncthreads();
    }

    // ---- epilogue: per-column bias, optional relu, fragment store ----
    float2 bn[4];
#pragma unroll
    for (int ni = 0; ni < 4; ni++) {
        int col = n0 + wn + ni * 8 + tl * 2;
        bn[ni] = *(const float2*)&b1e[col];
        if (MODE == 2) {
            float2 c2 = *(const float2*)&b2e[col];
            bn[ni].x += c2.x; bn[ni].y += c2.y;
        }
    }

    float* Cb;
    if (MODE == 1)      Cb = g_H   + (size_t)e * CAP * NDIM;
    else if (MODE == 2) Cb = g_MID + (size_t)e * CAP * NDIM;
    else                Cb = g_PO  + (size_t)e * CAP * NDIM;

#pragma unroll
    for (int mi = 0; mi < 4; mi++) {
        int r0 = m0 + wm + mi * 16 + group;
        int r1 = r0 + 8;
        float* crow0 = Cb + (size_t)r0 * NDIM;
        float* crow1 = Cb + (size_t)r1 * NDIM;
#pragma unroll
        for (int ni = 0; ni < 4; ni++) {
            int col = n0 + wn + ni * 8 + tl * 2;
            float2 v0, v1;
            v0.x = acc[mi][ni][0] + bn[ni].x;
            v0.y = acc[mi][ni][1] + bn[ni].y;
            v1.x = acc[mi][ni][2] + bn[ni].x;
            v1.y = acc[mi][ni][3] + bn[ni].y;
            if (RELU) {
                v0.x = fmaxf(v0.x, 0.f); v0.y = fmaxf(v0.y, 0.f);
                v1.x = fmaxf(v1.x, 0.f); v1.y = fmaxf(v1.y, 0.f);
            }
            if (r0 < mcount) *(float2*)&crow0[col] = v0;
            if (r1 < mcount) *(float2*)&crow1[col] = v1;
        }
    }
}

// =================================================================
// Combine: out[t] = w0 * PO[p0] + w1 * PO[p1]  (deterministic)
// =================================================================
__global__ void combine_kernel(float* __restrict__ out) {
    const int t = blockIdx.x;
    const int p0 = g_pairpos[2 * t], p1 = g_pairpos[2 * t + 1];
    const float w0 = g_pairw[2 * t], w1 = g_pairw[2 * t + 1];
    const float4* r0 = (const float4*)(g_PO + (size_t)p0 * DOUT);
    const float4* r1 = (const float4*)(g_PO + (size_t)p1 * DOUT);
    float4* o = (float4*)(out + (size_t)t * DOUT);
    for (int c = threadIdx.x; c < DOUT / 4; c += blockDim.x) {
        float4 a = r0[c], b = r1[c], v;
        v.x = w0 * a.x + w1 * b.x;
        v.y = w0 * a.y + w1 * b.y;
        v.z = w0 * a.z + w1 * b.z;
        v.w = w0 * a.w + w1 * b.w;
        o[c] = v;
    }
}

// =================================================================
// Launch
// =================================================================
extern "C" void kernel_launch(void* const* d_in, const int* in_sizes, int n_in,
                              void* d_out, int out_size) {
    (void)in_sizes; (void)n_in; (void)out_size;
    const float* x   = (const float*)d_in[0];
    const float* w1  = (const float*)d_in[1];
    const float* b1  = (const float*)d_in[2];
    const float* w2  = (const float*)d_in[3];
    const float* b2  = (const float*)d_in[4];
    const float* w3  = (const float*)d_in[5];
    const float* b3  = (const float*)d_in[6];
    const float* wp  = (const float*)d_in[7];
    const float* bp  = (const float*)d_in[8];
    const float* gw1 = (const float*)d_in[9];
    const float* gb1 = (const float*)d_in[10];
    const float* gw2 = (const float*)d_in[11];
    const float* gb2 = (const float*)d_in[12];
    float* out = (float*)d_out;

    reset_counts_kernel<<<1, 32>>>();

    // Gating GEMM (exact fp32): g1 = relu(x @ gw1 + gb1)
    {
        dim3 grid(GHID / 128, B_TOK / 128, 1);
        gating_gemm_kernel<<<grid, 256>>>(x, gw1, gb1);
    }

    // Top-2 + softmax + scatter
    gating_topk_scatter_kernel<<<B_TOK, 128>>>(gw2, gb2);

    // GEMM1 (tf32): H = relu(x[tok] @ w1[e] + b1[e])
    {
        dim3 grid(HID / 128, CAP / 128, NEXP);
        moe_mma_kernel<1, DIN, HID, true><<<grid, 256>>>(
            x, w1, nullptr, b1, nullptr);
    }

    // GEMM2 (tf32, fused wp): MID = relu([H | x] @ [w2; wp] + b2 + bp)
    {
        dim3 grid(HID / 128, CAP / 128, NEXP);
        moe_mma_kernel<2, HID + DIN, HID, true><<<grid, 256>>>(
            x, w2, wp, b2, bp);
    }

    // GEMM3 (tf32): PO = MID @ w3[e] + b3[e]
    {
        dim3 grid(DOUT / 128, CAP / 128, NEXP);
        moe_mma_kernel<3, HID, DOUT, false><<<grid, 256>>>(
            x, w3, nullptr, b3, nullptr);
    }

    // Weighted combine into output
    combine_kernel<<<B_TOK, 256>>>(out);
}